// round 2
// baseline (speedup 1.0000x reference)
#include <cuda_runtime.h>
#include <cstdint>

#define N_NODES 10000
#define DIN 128
#define H1 8
#define F1 64
#define C1 512            // H1*F1
#define E0 80000
#define NE (2*E0 + N_NODES)   // 170000
#define F2 64
#define NEG_SLOPE 0.2f

// ---------------- scratch (static device globals; no allocation) -------------
static __device__ int      g_src[NE];
static __device__ int      g_dst[NE];
static __device__ float    g_B1[DIN*C1];           // repacked W1 -> (K=128, Ncol=512)
static __device__ float    g_proj1[N_NODES*C1];    // layer-1 projections
static __device__ float    g_as1[N_NODES*H1];
static __device__ float    g_an1[N_NODES*H1];
static __device__ unsigned g_m1[N_NODES*H1];       // segment max (ordered-uint encoded)
static __device__ float    g_den1[N_NODES*H1];
static __device__ float    g_w1[NE*H1];            // exp(e - max) per (edge, head)
static __device__ float    g_hbuf[N_NODES*C1];     // layer-1 output (after agg, then ELU)
static __device__ float    g_proj2[N_NODES*F2];
static __device__ float    g_as2[N_NODES];
static __device__ float    g_an2[N_NODES];
static __device__ unsigned g_m2[N_NODES];
static __device__ float    g_den2[N_NODES];
static __device__ float    g_w2[NE];

// ordered-uint encoding of float for atomicMax
__device__ __forceinline__ unsigned fenc(float f) {
    unsigned u = __float_as_uint(f);
    return (u & 0x80000000u) ? ~u : (u | 0x80000000u);
}
__device__ __forceinline__ float fdec(unsigned u) {
    return (u & 0x80000000u) ? __uint_as_float(u & 0x7fffffffu)
                             : __uint_as_float(~u);
}
#define ENC_NEG_INF 0x007FFFFFu   // fenc(-inf)

// ---------------- init: zero accumulators, set maxes to -inf -----------------
__global__ void init_kernel(float* __restrict__ out) {
    int stride = gridDim.x * blockDim.x;
    int tid = blockIdx.x * blockDim.x + threadIdx.x;
    for (int i = tid; i < N_NODES*C1; i += stride) g_hbuf[i] = 0.f;
    for (int i = tid; i < N_NODES*H1; i += stride) { g_den1[i] = 0.f; g_m1[i] = ENC_NEG_INF; }
    for (int i = tid; i < N_NODES;    i += stride) { g_den2[i] = 0.f; g_m2[i] = ENC_NEG_INF; }
    for (int i = tid; i < N_NODES*F2; i += stride) out[i] = 0.f;
}

// ---------------- edge list (bidirectional + self loops) ---------------------
// Dtype-robust decode: edges may be int32 (JAX x64 disabled demotes int64) or
// true int64. If int64 little-endian with values < 2^31, odd int32 words of the
// buffer are all zero; if int32, they are random node ids. Probe 4 odd words —
// deterministic, same answer for every thread, no host sync needed.
__global__ void build_edges(const int* __restrict__ e32) {
    bool is64 = (e32[1] == 0) && (e32[3] == 0) && (e32[5] == 0) && (e32[7] == 0);
    int i = blockIdx.x * blockDim.x + threadIdx.x;
    if (i >= NE) return;
    int s, d;
    if (i < NE - N_NODES) {
        int j = (i < E0) ? i : (i - E0);
        int si = (i < E0) ? j : (E0 + j);      // index into logical edges[] flat (2*E0)
        int di = (i < E0) ? (E0 + j) : j;
        s = is64 ? e32[2*si] : e32[si];
        d = is64 ? e32[2*di] : e32[di];
    } else {
        s = i - (NE - N_NODES); d = s;
    }
    // clamp defensively: wrong decode -> wrong answer (rel_err), never a crash
    s = min(max(s, 0), N_NODES - 1);
    d = min(max(d, 0), N_NODES - 1);
    g_src[i] = s; g_dst[i] = d;
}

// ---------------- repack W1 (H,Din,F1) -> (Din, H*F1) ------------------------
__global__ void repack_w1(const float* __restrict__ W1) {
    int i = blockIdx.x * blockDim.x + threadIdx.x;
    if (i >= DIN*C1) return;
    int d = i / C1, c = i % C1;
    int h = c >> 6, f = c & 63;
    g_B1[i] = W1[(h*DIN + d)*F1 + f];
}

// ---------------- register-tiled fp32 GEMM (64x64 tile, 4x4/thread) ----------
// A: MxK row-major, B: KxN row-major, C: MxN row-major. N%64==0, K%16==0.
__device__ __forceinline__ void sgemm_tile(const float* __restrict__ A,
                                           const float* __restrict__ B,
                                           float* __restrict__ C,
                                           int M, int N, int K) {
    __shared__ __align__(16) float As[16][68];
    __shared__ __align__(16) float Bs[16][64];
    const int tid = threadIdx.x;
    const int tx = tid & 15, ty = tid >> 4;
    const int row0 = blockIdx.y * 64;
    const int col0 = blockIdx.x * 64;
    float acc[4][4];
#pragma unroll
    for (int i = 0; i < 4; i++)
#pragma unroll
        for (int j = 0; j < 4; j++) acc[i][j] = 0.f;

    for (int k0 = 0; k0 < K; k0 += 16) {
#pragma unroll
        for (int l = 0; l < 4; l++) {
            int i = tid + l*256;
            int r = i >> 4, kk = i & 15;
            int gr = row0 + r;
            As[kk][r] = (gr < M) ? A[(size_t)gr*K + k0 + kk] : 0.f;
        }
#pragma unroll
        for (int l = 0; l < 4; l++) {
            int i = tid + l*256;
            int kk = i >> 6, c = i & 63;
            Bs[kk][c] = B[(size_t)(k0 + kk)*N + col0 + c];
        }
        __syncthreads();
#pragma unroll
        for (int kk = 0; kk < 16; kk++) {
            float4 av = *(const float4*)&As[kk][ty*4];
            float4 bv = *(const float4*)&Bs[kk][tx*4];
            float a[4] = {av.x, av.y, av.z, av.w};
            float b[4] = {bv.x, bv.y, bv.z, bv.w};
#pragma unroll
            for (int i = 0; i < 4; i++)
#pragma unroll
                for (int j = 0; j < 4; j++) acc[i][j] += a[i]*b[j];
        }
        __syncthreads();
    }
#pragma unroll
    for (int i = 0; i < 4; i++) {
        int gr = row0 + ty*4 + i;
        if (gr < M) {
            float4 v = make_float4(acc[i][0], acc[i][1], acc[i][2], acc[i][3]);
            *(float4*)&C[(size_t)gr*N + col0 + tx*4] = v;
        }
    }
}

__global__ void gemm1_kernel(const float* __restrict__ x) {
    sgemm_tile(x, g_B1, g_proj1, N_NODES, C1, DIN);
}
__global__ void gemm2_kernel(const float* __restrict__ W2) {
    sgemm_tile(g_hbuf, W2, g_proj2, N_NODES, F2, C1);
}

// ---------------- attention coefficients (dot of proj row chunk with a) ------
__global__ void alpha1_kernel(const float* __restrict__ a1) {
    int t = blockIdx.x * blockDim.x + threadIdx.x;
    int w = t >> 5, lane = t & 31;
    if (w >= N_NODES*H1) return;
    int n = w / H1, h = w % H1;
    const float* p = g_proj1 + (size_t)n*C1 + h*F1;
    float v0 = p[lane], v1 = p[lane + 32];
    const float* av = a1 + h*2*F1;
    float s  = v0*av[lane]      + v1*av[lane + 32];
    float tn = v0*av[F1 + lane] + v1*av[F1 + lane + 32];
#pragma unroll
    for (int o = 16; o; o >>= 1) {
        s  += __shfl_xor_sync(0xffffffffu, s, o);
        tn += __shfl_xor_sync(0xffffffffu, tn, o);
    }
    if (!lane) { g_as1[w] = s; g_an1[w] = tn; }
}

__global__ void alpha2_kernel(const float* __restrict__ a2) {
    int t = blockIdx.x * blockDim.x + threadIdx.x;
    int w = t >> 5, lane = t & 31;
    if (w >= N_NODES) return;
    const float* p = g_proj2 + (size_t)w*F2;
    float v0 = p[lane], v1 = p[lane + 32];
    float s  = v0*a2[lane]      + v1*a2[lane + 32];
    float tn = v0*a2[F2 + lane] + v1*a2[F2 + lane + 32];
#pragma unroll
    for (int o = 16; o; o >>= 1) {
        s  += __shfl_xor_sync(0xffffffffu, s, o);
        tn += __shfl_xor_sync(0xffffffffu, tn, o);
    }
    if (!lane) { g_as2[w] = s; g_an2[w] = tn; }
}

// ---------------- edge softmax: max pass, exp+sum pass -----------------------
__global__ void edge_max1() {
    int idx = blockIdx.x * blockDim.x + threadIdx.x;
    if (idx >= NE*H1) return;
    int e = idx >> 3, h = idx & 7;
    int s = g_src[e], d = g_dst[e];
    float v = g_as1[d*H1 + h] + g_an1[s*H1 + h];
    v = (v >= 0.f) ? v : NEG_SLOPE*v;
    atomicMax(&g_m1[d*H1 + h], fenc(v));
}
__global__ void edge_exp1() {
    int idx = blockIdx.x * blockDim.x + threadIdx.x;
    if (idx >= NE*H1) return;
    int e = idx >> 3, h = idx & 7;
    int s = g_src[e], d = g_dst[e];
    float v = g_as1[d*H1 + h] + g_an1[s*H1 + h];
    v = (v >= 0.f) ? v : NEG_SLOPE*v;
    float w = expf(v - fdec(g_m1[d*H1 + h]));
    g_w1[idx] = w;
    atomicAdd(&g_den1[d*H1 + h], w);
}
__global__ void edge_max2() {
    int e = blockIdx.x * blockDim.x + threadIdx.x;
    if (e >= NE) return;
    int s = g_src[e], d = g_dst[e];
    float v = g_as2[d] + g_an2[s];
    v = (v >= 0.f) ? v : NEG_SLOPE*v;
    atomicMax(&g_m2[d], fenc(v));
}
__global__ void edge_exp2() {
    int e = blockIdx.x * blockDim.x + threadIdx.x;
    if (e >= NE) return;
    int s = g_src[e], d = g_dst[e];
    float v = g_as2[d] + g_an2[s];
    v = (v >= 0.f) ? v : NEG_SLOPE*v;
    float w = expf(v - fdec(g_m2[d]));
    g_w2[e] = w;
    atomicAdd(&g_den2[d], w);
}

// ---------------- weighted aggregation (scatter-add) -------------------------
// one warp per (edge, head): 64 features, 2 floats/lane
__global__ void aggregate1() {
    int t = blockIdx.x * blockDim.x + threadIdx.x;
    int w = t >> 5, lane = t & 31;
    if (w >= NE*H1) return;
    int e = w >> 3, h = w & 7;
    int s = g_src[e], d = g_dst[e];
    float wgt = g_w1[w] / g_den1[d*H1 + h];
    const float2 v = *(const float2*)&g_proj1[(size_t)s*C1 + h*F1 + lane*2];
    float* dstp = &g_hbuf[(size_t)d*C1 + h*F1 + lane*2];
    atomicAdd(dstp,     v.x * wgt);
    atomicAdd(dstp + 1, v.y * wgt);
}
// one warp per edge: 64 features
__global__ void aggregate2(float* __restrict__ out) {
    int t = blockIdx.x * blockDim.x + threadIdx.x;
    int e = t >> 5, lane = t & 31;
    if (e >= NE) return;
    int s = g_src[e], d = g_dst[e];
    float wgt = g_w2[e] / g_den2[d];
    const float2 v = *(const float2*)&g_proj2[(size_t)s*F2 + lane*2];
    float* dstp = &out[(size_t)d*F2 + lane*2];
    atomicAdd(dstp,     v.x * wgt);
    atomicAdd(dstp + 1, v.y * wgt);
}

// ---------------- ELU ---------------------------------------------------------
__global__ void elu_kernel() {
    int i = blockIdx.x * blockDim.x + threadIdx.x;
    if (i >= N_NODES*C1) return;
    float x = g_hbuf[i];
    g_hbuf[i] = (x > 0.f) ? x : expm1f(x);
}

// ---------------- launch -------------------------------------------------------
extern "C" void kernel_launch(void* const* d_in, const int* in_sizes, int n_in,
                              void* d_out, int out_size) {
    const float* x     = (const float*)d_in[0];
    const int*   edges = (const int*)d_in[1];   // dtype probed in build_edges
    const float* W1    = (const float*)d_in[2];
    const float* a1    = (const float*)d_in[3];
    const float* W2    = (const float*)d_in[4];
    const float* a2    = (const float*)d_in[5];
    float* out = (float*)d_out;

    init_kernel<<<512, 256>>>(out);
    build_edges<<<(NE + 255)/256, 256>>>(edges);
    repack_w1<<<(DIN*C1 + 255)/256, 256>>>(W1);

    // layer 1
    gemm1_kernel<<<dim3(C1/64, (N_NODES + 63)/64), 256>>>(x);
    alpha1_kernel<<<(N_NODES*H1*32 + 255)/256, 256>>>(a1);
    edge_max1<<<(NE*H1 + 255)/256, 256>>>();
    edge_exp1<<<(NE*H1 + 255)/256, 256>>>();
    aggregate1<<<(NE*H1*32 + 255)/256, 256>>>();
    elu_kernel<<<(N_NODES*C1 + 255)/256, 256>>>();

    // layer 2
    gemm2_kernel<<<dim3(F2/64, (N_NODES + 63)/64), 256>>>(W2);
    alpha2_kernel<<<(N_NODES*32 + 255)/256, 256>>>(a2);
    edge_max2<<<(NE + 255)/256, 256>>>();
    edge_exp2<<<(NE + 255)/256, 256>>>();
    aggregate2<<<(NE*32 + 255)/256, 256>>>(out);
}

// round 3
// speedup vs baseline: 1.5543x; 1.5543x over previous
#include <cuda_runtime.h>
#include <cstdint>

#define N_NODES 10000
#define DIN 128
#define H1 8
#define F1 64
#define C1 512            // H1*F1
#define E0 80000
#define NE (2*E0 + N_NODES)   // 170000
#define F2 64
#define NEG_SLOPE 0.2f

// ---------------- scratch (static device globals; no allocation) -------------
static __device__ int   g_src[NE];
static __device__ int   g_dst[NE];
static __device__ int   g_cnt[N_NODES];
static __device__ int   g_cursor[N_NODES];
static __device__ int   g_rowptr[N_NODES + 1];
static __device__ int   g_nbr[NE];                 // CSR by dst: src indices
static __device__ float g_B1[DIN*C1];              // repacked W1 -> (K, H*F1)
static __device__ float g_proj1[N_NODES*C1];
static __device__ float g_as1[N_NODES*H1];
static __device__ float g_an1[N_NODES*H1];
static __device__ float g_hbuf[N_NODES*C1];        // layer-1 output (post ELU)
static __device__ float g_proj2[N_NODES*F2];
static __device__ float g_as2[N_NODES];
static __device__ float g_an2[N_NODES];

// ---------------- init: zero CSR counters ------------------------------------
__global__ void init_kernel() {
    int tid = blockIdx.x * blockDim.x + threadIdx.x;
    if (tid < N_NODES) { g_cnt[tid] = 0; g_cursor[tid] = 0; }
}

// ---------------- edge list + in-degree count --------------------------------
// Dtype probe: if edges are int64 LE with values < 2^31, odd 32-bit words are 0.
__global__ void build_edges(const int* __restrict__ e32) {
    bool is64 = (e32[1] == 0) && (e32[3] == 0) && (e32[5] == 0) && (e32[7] == 0);
    int i = blockIdx.x * blockDim.x + threadIdx.x;
    if (i >= NE) return;
    int s, d;
    if (i < NE - N_NODES) {
        int j  = (i < E0) ? i : (i - E0);
        int si = (i < E0) ? j : (E0 + j);
        int di = (i < E0) ? (E0 + j) : j;
        s = is64 ? e32[2*si] : e32[si];
        d = is64 ? e32[2*di] : e32[di];
    } else {
        s = i - (NE - N_NODES); d = s;
    }
    s = min(max(s, 0), N_NODES - 1);
    d = min(max(d, 0), N_NODES - 1);
    g_src[i] = s; g_dst[i] = d;
    atomicAdd(&g_cnt[d], 1);
}

// ---------------- exclusive scan of in-degrees (single block) ----------------
__global__ void scan_kernel() {
    __shared__ int ssum[1024];
    const int t = threadIdx.x;
    const int per = (N_NODES + 1023) / 1024;   // 10
    int base = t * per;
    int loc[16];
    int s = 0;
#pragma unroll
    for (int i = 0; i < per; i++) {
        int idx = base + i;
        int v = (idx < N_NODES) ? g_cnt[idx] : 0;
        loc[i] = v; s += v;
    }
    ssum[t] = s;
    __syncthreads();
    for (int off = 1; off < 1024; off <<= 1) {
        int v = (t >= off) ? ssum[t - off] : 0;
        __syncthreads();
        ssum[t] += v;
        __syncthreads();
    }
    int run = (t > 0) ? ssum[t - 1] : 0;
#pragma unroll
    for (int i = 0; i < per; i++) {
        int idx = base + i;
        if (idx < N_NODES) { g_rowptr[idx] = run; run += loc[i]; }
    }
    if (t == 1023) g_rowptr[N_NODES] = NE;
}

__global__ void fill_csr() {
    int e = blockIdx.x * blockDim.x + threadIdx.x;
    if (e >= NE) return;
    int d = g_dst[e];
    int slot = atomicAdd(&g_cursor[d], 1);
    g_nbr[g_rowptr[d] + slot] = g_src[e];
}

// ---------------- repack W1 (H,Din,F1) -> (Din, H*F1) ------------------------
__global__ void repack_w1(const float* __restrict__ W1) {
    int i = blockIdx.x * blockDim.x + threadIdx.x;
    if (i >= DIN*C1) return;
    int d = i / C1, c = i % C1;
    int h = c >> 6, f = c & 63;
    g_B1[i] = W1[(h*DIN + d)*F1 + f];
}

// ---------------- GEMM1: 128x128 tile, 8x8/thread ----------------------------
__global__ __launch_bounds__(256) void gemm1_kernel(const float* __restrict__ A) {
    __shared__ __align__(16) float As[8][132];
    __shared__ __align__(16) float Bs[8][128];
    const int tid = threadIdx.x;
    const int tx = tid & 15, ty = tid >> 4;
    const int row0 = blockIdx.y * 128;
    const int col0 = blockIdx.x * 128;
    const int M = N_NODES, N = C1, K = DIN;

    float acc[8][8];
#pragma unroll
    for (int i = 0; i < 8; i++)
#pragma unroll
        for (int j = 0; j < 8; j++) acc[i][j] = 0.f;

    const int ar = tid >> 1;           // A row within tile (0..127)
    const int akq = (tid & 1) * 4;     // which float4 along K
    const int bk = tid >> 5;           // B k row (0..7)
    const int bc = (tid & 31) * 4;     // B col (0..124)

    for (int k0 = 0; k0 < K; k0 += 8) {
        int gr = row0 + ar;
        float4 va = (gr < M) ? *(const float4*)&A[(size_t)gr*K + k0 + akq]
                             : make_float4(0.f, 0.f, 0.f, 0.f);
        As[akq + 0][ar] = va.x;
        As[akq + 1][ar] = va.y;
        As[akq + 2][ar] = va.z;
        As[akq + 3][ar] = va.w;
        *(float4*)&Bs[bk][bc] = *(const float4*)&g_B1[(size_t)(k0 + bk)*N + col0 + bc];
        __syncthreads();
#pragma unroll
        for (int k = 0; k < 8; k++) {
            float4 a0 = *(const float4*)&As[k][ty*8];
            float4 a1 = *(const float4*)&As[k][ty*8 + 4];
            float4 b0 = *(const float4*)&Bs[k][tx*8];
            float4 b1 = *(const float4*)&Bs[k][tx*8 + 4];
            float a[8] = {a0.x,a0.y,a0.z,a0.w,a1.x,a1.y,a1.z,a1.w};
            float b[8] = {b0.x,b0.y,b0.z,b0.w,b1.x,b1.y,b1.z,b1.w};
#pragma unroll
            for (int i = 0; i < 8; i++)
#pragma unroll
                for (int j = 0; j < 8; j++) acc[i][j] += a[i]*b[j];
        }
        __syncthreads();
    }
#pragma unroll
    for (int i = 0; i < 8; i++) {
        int gr = row0 + ty*8 + i;
        if (gr < M) {
            *(float4*)&g_proj1[(size_t)gr*N + col0 + tx*8]     =
                make_float4(acc[i][0], acc[i][1], acc[i][2], acc[i][3]);
            *(float4*)&g_proj1[(size_t)gr*N + col0 + tx*8 + 4] =
                make_float4(acc[i][4], acc[i][5], acc[i][6], acc[i][7]);
        }
    }
}

// ---------------- GEMM2 (64x64 tile, 4x4/thread) -----------------------------
__global__ void gemm2_kernel(const float* __restrict__ B) {
    __shared__ __align__(16) float As[16][68];
    __shared__ __align__(16) float Bs[16][64];
    const float* A = g_hbuf;
    float* C = g_proj2;
    const int M = N_NODES, N = F2, K = C1;
    const int tid = threadIdx.x;
    const int tx = tid & 15, ty = tid >> 4;
    const int row0 = blockIdx.y * 64;
    const int col0 = blockIdx.x * 64;
    float acc[4][4];
#pragma unroll
    for (int i = 0; i < 4; i++)
#pragma unroll
        for (int j = 0; j < 4; j++) acc[i][j] = 0.f;

    for (int k0 = 0; k0 < K; k0 += 16) {
#pragma unroll
        for (int l = 0; l < 4; l++) {
            int i = tid + l*256;
            int r = i >> 4, kk = i & 15;
            int gr = row0 + r;
            As[kk][r] = (gr < M) ? A[(size_t)gr*K + k0 + kk] : 0.f;
        }
#pragma unroll
        for (int l = 0; l < 4; l++) {
            int i = tid + l*256;
            int kk = i >> 6, c = i & 63;
            Bs[kk][c] = B[(size_t)(k0 + kk)*N + col0 + c];
        }
        __syncthreads();
#pragma unroll
        for (int kk = 0; kk < 16; kk++) {
            float4 av = *(const float4*)&As[kk][ty*4];
            float4 bv = *(const float4*)&Bs[kk][tx*4];
            float a[4] = {av.x, av.y, av.z, av.w};
            float b[4] = {bv.x, bv.y, bv.z, bv.w};
#pragma unroll
            for (int i = 0; i < 4; i++)
#pragma unroll
                for (int j = 0; j < 4; j++) acc[i][j] += a[i]*b[j];
        }
        __syncthreads();
    }
#pragma unroll
    for (int i = 0; i < 4; i++) {
        int gr = row0 + ty*4 + i;
        if (gr < M) {
            *(float4*)&C[(size_t)gr*N + col0 + tx*4] =
                make_float4(acc[i][0], acc[i][1], acc[i][2], acc[i][3]);
        }
    }
}

// ---------------- attention coefficients -------------------------------------
__global__ void alpha1_kernel(const float* __restrict__ a1) {
    int t = blockIdx.x * blockDim.x + threadIdx.x;
    int w = t >> 5, lane = t & 31;
    if (w >= N_NODES*H1) return;
    int n = w / H1, h = w % H1;
    const float* p = g_proj1 + (size_t)n*C1 + h*F1;
    float v0 = p[lane], v1 = p[lane + 32];
    const float* av = a1 + h*2*F1;
    float s  = v0*av[lane]      + v1*av[lane + 32];
    float tn = v0*av[F1 + lane] + v1*av[F1 + lane + 32];
#pragma unroll
    for (int o = 16; o; o >>= 1) {
        s  += __shfl_xor_sync(0xffffffffu, s, o);
        tn += __shfl_xor_sync(0xffffffffu, tn, o);
    }
    if (!lane) { g_as1[w] = s; g_an1[w] = tn; }
}

__global__ void alpha2_kernel(const float* __restrict__ a2) {
    int t = blockIdx.x * blockDim.x + threadIdx.x;
    int w = t >> 5, lane = t & 31;
    if (w >= N_NODES) return;
    const float* p = g_proj2 + (size_t)w*F2;
    float v0 = p[lane], v1 = p[lane + 32];
    float s  = v0*a2[lane]      + v1*a2[lane + 32];
    float tn = v0*a2[F2 + lane] + v1*a2[F2 + lane + 32];
#pragma unroll
    for (int o = 16; o; o >>= 1) {
        s  += __shfl_xor_sync(0xffffffffu, s, o);
        tn += __shfl_xor_sync(0xffffffffu, tn, o);
    }
    if (!lane) { g_as2[w] = s; g_an2[w] = tn; }
}

// ---------------- fused gather: softmax + weighted agg + ELU (layer 1) -------
// one warp per (node, head)
__global__ void gather1() {
    int t = blockIdx.x * blockDim.x + threadIdx.x;
    int w = t >> 5, lane = t & 31;
    if (w >= N_NODES*H1) return;
    int n = w >> 3, h = w & 7;
    int beg = g_rowptr[n], end = g_rowptr[n + 1];
    float as = g_as1[n*H1 + h];

    // pass 1: segment max
    float mx = -3.0e38f;
    for (int i = beg + lane; i < end; i += 32) {
        int s = g_nbr[i];
        float v = as + g_an1[s*H1 + h];
        v = (v >= 0.f) ? v : NEG_SLOPE*v;
        mx = fmaxf(mx, v);
    }
#pragma unroll
    for (int o = 16; o; o >>= 1) mx = fmaxf(mx, __shfl_xor_sync(0xffffffffu, mx, o));

    // pass 2: exp-weighted feature accumulation
    float acc0 = 0.f, acc1 = 0.f, den = 0.f;
    for (int i = beg; i < end; i++) {
        int s = g_nbr[i];                       // broadcast load
        float v = as + g_an1[s*H1 + h];         // broadcast load
        v = (v >= 0.f) ? v : NEG_SLOPE*v;
        float wgt = __expf(v - mx);
        den += wgt;
        float2 p = *(const float2*)&g_proj1[(size_t)s*C1 + h*F1 + lane*2];
        acc0 += wgt * p.x;
        acc1 += wgt * p.y;
    }
    float inv = 1.f / den;
    acc0 *= inv; acc1 *= inv;
    acc0 = (acc0 > 0.f) ? acc0 : expm1f(acc0);   // ELU fused
    acc1 = (acc1 > 0.f) ? acc1 : expm1f(acc1);
    *(float2*)&g_hbuf[(size_t)n*C1 + h*F1 + lane*2] = make_float2(acc0, acc1);
}

// ---------------- fused gather layer 2 (H2=1, mean == identity) --------------
__global__ void gather2(float* __restrict__ out) {
    int t = blockIdx.x * blockDim.x + threadIdx.x;
    int w = t >> 5, lane = t & 31;
    if (w >= N_NODES) return;
    int n = w;
    int beg = g_rowptr[n], end = g_rowptr[n + 1];
    float as = g_as2[n];

    float mx = -3.0e38f;
    for (int i = beg + lane; i < end; i += 32) {
        int s = g_nbr[i];
        float v = as + g_an2[s];
        v = (v >= 0.f) ? v : NEG_SLOPE*v;
        mx = fmaxf(mx, v);
    }
#pragma unroll
    for (int o = 16; o; o >>= 1) mx = fmaxf(mx, __shfl_xor_sync(0xffffffffu, mx, o));

    float acc0 = 0.f, acc1 = 0.f, den = 0.f;
    for (int i = beg; i < end; i++) {
        int s = g_nbr[i];
        float v = as + g_an2[s];
        v = (v >= 0.f) ? v : NEG_SLOPE*v;
        float wgt = __expf(v - mx);
        den += wgt;
        float2 p = *(const float2*)&g_proj2[(size_t)s*F2 + lane*2];
        acc0 += wgt * p.x;
        acc1 += wgt * p.y;
    }
    float inv = 1.f / den;
    *(float2*)&out[(size_t)n*F2 + lane*2] = make_float2(acc0*inv, acc1*inv);
}

// ---------------- launch -------------------------------------------------------
extern "C" void kernel_launch(void* const* d_in, const int* in_sizes, int n_in,
                              void* d_out, int out_size) {
    const float* x     = (const float*)d_in[0];
    const int*   edges = (const int*)d_in[1];
    const float* W1    = (const float*)d_in[2];
    const float* a1    = (const float*)d_in[3];
    const float* W2    = (const float*)d_in[4];
    const float* a2    = (const float*)d_in[5];
    float* out = (float*)d_out;

    // graph prep
    init_kernel<<<(N_NODES + 255)/256, 256>>>();
    build_edges<<<(NE + 255)/256, 256>>>(edges);
    scan_kernel<<<1, 1024>>>();
    fill_csr<<<(NE + 255)/256, 256>>>();
    repack_w1<<<(DIN*C1 + 255)/256, 256>>>(W1);

    // layer 1
    gemm1_kernel<<<dim3(C1/128, (N_NODES + 127)/128), 256>>>(x);
    alpha1_kernel<<<(N_NODES*H1*32 + 255)/256, 256>>>(a1);
    gather1<<<(N_NODES*H1*32 + 255)/256, 256>>>();

    // layer 2
    gemm2_kernel<<<dim3(F2/64, (N_NODES + 63)/64), 256>>>(W2);
    alpha2_kernel<<<(N_NODES*32 + 255)/256, 256>>>(a2);
    gather2<<<(N_NODES*32 + 255)/256, 256>>>(out);
}

// round 4
// speedup vs baseline: 1.7066x; 1.0980x over previous
#include <cuda_runtime.h>
#include <cstdint>

#define N_NODES 10000
#define DIN 128
#define H1 8
#define F1 64
#define C1 512            // H1*F1
#define E0 80000
#define NE (2*E0 + N_NODES)   // 170000
#define F2 64
#define NEG_SLOPE 0.2f
#define FULL 0xffffffffu

// ---------------- scratch (static device globals; no allocation) -------------
static __device__ int   g_src[NE];
static __device__ int   g_dst[NE];
static __device__ int   g_cnt[N_NODES];
static __device__ int   g_cursor[N_NODES];
static __device__ int   g_rowptr[N_NODES + 1];
static __device__ int   g_nbr[NE];                 // CSR by dst: src indices
static __device__ float g_B1[DIN*C1];              // repacked W1 -> (K, H*F1)
static __device__ float g_proj1[N_NODES*C1];
static __device__ float g_as1[N_NODES*H1];
static __device__ float g_an1[N_NODES*H1];
static __device__ float g_hbuf[N_NODES*C1];        // layer-1 output (post ELU)
static __device__ float g_p2part[4*N_NODES*F2];    // split-K partials for gemm2
static __device__ float g_proj2[N_NODES*F2];
static __device__ float g_as2[N_NODES];
static __device__ float g_an2[N_NODES];

// ---------------- edge list + in-degree count --------------------------------
// Dtype probe: if edges are int64 LE with values < 2^31, odd 32-bit words are 0.
__global__ void build_edges(const int* __restrict__ e32) {
    bool is64 = (e32[1] == 0) && (e32[3] == 0) && (e32[5] == 0) && (e32[7] == 0);
    int i = blockIdx.x * blockDim.x + threadIdx.x;
    if (i >= NE) return;
    int s, d;
    if (i < NE - N_NODES) {
        int j  = (i < E0) ? i : (i - E0);
        int si = (i < E0) ? j : (E0 + j);
        int di = (i < E0) ? (E0 + j) : j;
        s = is64 ? e32[2*si] : e32[si];
        d = is64 ? e32[2*di] : e32[di];
    } else {
        s = i - (NE - N_NODES); d = s;
    }
    s = min(max(s, 0), N_NODES - 1);
    d = min(max(d, 0), N_NODES - 1);
    g_src[i] = s; g_dst[i] = d;
    atomicAdd(&g_cnt[d], 1);
}

// ---------------- exclusive scan of in-degrees (single block) ----------------
__global__ void scan_kernel() {
    __shared__ int ssum[1024];
    const int t = threadIdx.x;
    const int per = (N_NODES + 1023) / 1024;   // 10
    int base = t * per;
    int loc[16];
    int s = 0;
#pragma unroll
    for (int i = 0; i < per; i++) {
        int idx = base + i;
        int v = (idx < N_NODES) ? g_cnt[idx] : 0;
        loc[i] = v; s += v;
    }
    ssum[t] = s;
    __syncthreads();
    for (int off = 1; off < 1024; off <<= 1) {
        int v = (t >= off) ? ssum[t - off] : 0;
        __syncthreads();
        ssum[t] += v;
        __syncthreads();
    }
    int run = (t > 0) ? ssum[t - 1] : 0;
#pragma unroll
    for (int i = 0; i < per; i++) {
        int idx = base + i;
        if (idx < N_NODES) { g_rowptr[idx] = run; run += loc[i]; }
    }
    if (t == 1023) g_rowptr[N_NODES] = NE;
}

__global__ void fill_csr() {
    int e = blockIdx.x * blockDim.x + threadIdx.x;
    if (e >= NE) return;
    int d = g_dst[e];
    int slot = atomicAdd(&g_cursor[d], 1);
    g_nbr[g_rowptr[d] + slot] = g_src[e];
}

// ---------------- repack W1 (H,Din,F1) -> (Din, H*F1) ------------------------
__global__ void repack_w1(const float* __restrict__ W1) {
    int i = blockIdx.x * blockDim.x + threadIdx.x;
    if (i >= DIN*C1) return;
    int d = i / C1, c = i % C1;
    int h = c >> 6, f = c & 63;
    g_B1[i] = W1[(h*DIN + d)*F1 + f];
}

// ---------------- GEMM1: 128x128 tile, 8x8/thread ----------------------------
__global__ __launch_bounds__(256) void gemm1_kernel(const float* __restrict__ A) {
    __shared__ __align__(16) float As[8][132];
    __shared__ __align__(16) float Bs[8][128];
    const int tid = threadIdx.x;
    const int tx = tid & 15, ty = tid >> 4;
    const int row0 = blockIdx.y * 128;
    const int col0 = blockIdx.x * 128;
    const int M = N_NODES, N = C1, K = DIN;

    float acc[8][8];
#pragma unroll
    for (int i = 0; i < 8; i++)
#pragma unroll
        for (int j = 0; j < 8; j++) acc[i][j] = 0.f;

    const int ar = tid >> 1;
    const int akq = (tid & 1) * 4;
    const int bk = tid >> 5;
    const int bc = (tid & 31) * 4;

    for (int k0 = 0; k0 < K; k0 += 8) {
        int gr = row0 + ar;
        float4 va = (gr < M) ? *(const float4*)&A[(size_t)gr*K + k0 + akq]
                             : make_float4(0.f, 0.f, 0.f, 0.f);
        As[akq + 0][ar] = va.x;
        As[akq + 1][ar] = va.y;
        As[akq + 2][ar] = va.z;
        As[akq + 3][ar] = va.w;
        *(float4*)&Bs[bk][bc] = *(const float4*)&g_B1[(size_t)(k0 + bk)*N + col0 + bc];
        __syncthreads();
#pragma unroll
        for (int k = 0; k < 8; k++) {
            float4 a0 = *(const float4*)&As[k][ty*8];
            float4 a1 = *(const float4*)&As[k][ty*8 + 4];
            float4 b0 = *(const float4*)&Bs[k][tx*8];
            float4 b1 = *(const float4*)&Bs[k][tx*8 + 4];
            float a[8] = {a0.x,a0.y,a0.z,a0.w,a1.x,a1.y,a1.z,a1.w};
            float b[8] = {b0.x,b0.y,b0.z,b0.w,b1.x,b1.y,b1.z,b1.w};
#pragma unroll
            for (int i = 0; i < 8; i++)
#pragma unroll
                for (int j = 0; j < 8; j++) acc[i][j] += a[i]*b[j];
        }
        __syncthreads();
    }
#pragma unroll
    for (int i = 0; i < 8; i++) {
        int gr = row0 + ty*8 + i;
        if (gr < M) {
            *(float4*)&g_proj1[(size_t)gr*N + col0 + tx*8]     =
                make_float4(acc[i][0], acc[i][1], acc[i][2], acc[i][3]);
            *(float4*)&g_proj1[(size_t)gr*N + col0 + tx*8 + 4] =
                make_float4(acc[i][4], acc[i][5], acc[i][6], acc[i][7]);
        }
    }
}

// ---------------- GEMM2 split-K: 64x64 tile, K-chunk 128 per z ---------------
__global__ void gemm2_kernel(const float* __restrict__ B) {
    __shared__ __align__(16) float As[16][68];
    __shared__ __align__(16) float Bs[16][64];
    const float* A = g_hbuf;
    const int M = N_NODES, N = F2, K = C1;
    const int tid = threadIdx.x;
    const int tx = tid & 15, ty = tid >> 4;
    const int row0 = blockIdx.y * 64;
    const int kz0 = blockIdx.z * (K/4);
    float* C = g_p2part + (size_t)blockIdx.z * N_NODES * F2;
    float acc[4][4];
#pragma unroll
    for (int i = 0; i < 4; i++)
#pragma unroll
        for (int j = 0; j < 4; j++) acc[i][j] = 0.f;

    for (int k0 = kz0; k0 < kz0 + K/4; k0 += 16) {
#pragma unroll
        for (int l = 0; l < 4; l++) {
            int i = tid + l*256;
            int r = i >> 4, kk = i & 15;
            int gr = row0 + r;
            As[kk][r] = (gr < M) ? A[(size_t)gr*K + k0 + kk] : 0.f;
        }
        {
            int kk = tid >> 6, c = tid & 63;
            Bs[kk][c]      = B[(size_t)(k0 + kk)*N + c];
            Bs[kk + 4][c]  = B[(size_t)(k0 + kk + 4)*N + c];
            Bs[kk + 8][c]  = B[(size_t)(k0 + kk + 8)*N + c];
            Bs[kk + 12][c] = B[(size_t)(k0 + kk + 12)*N + c];
        }
        __syncthreads();
#pragma unroll
        for (int kk = 0; kk < 16; kk++) {
            float4 av = *(const float4*)&As[kk][ty*4];
            float4 bv = *(const float4*)&Bs[kk][tx*4];
            float a[4] = {av.x, av.y, av.z, av.w};
            float b[4] = {bv.x, bv.y, bv.z, bv.w};
#pragma unroll
            for (int i = 0; i < 4; i++)
#pragma unroll
                for (int j = 0; j < 4; j++) acc[i][j] += a[i]*b[j];
        }
        __syncthreads();
    }
#pragma unroll
    for (int i = 0; i < 4; i++) {
        int gr = row0 + ty*4 + i;
        if (gr < M) {
            *(float4*)&C[(size_t)gr*N + tx*4] =
                make_float4(acc[i][0], acc[i][1], acc[i][2], acc[i][3]);
        }
    }
}

// ---------------- attention coefficients (layer 1) ---------------------------
__global__ void alpha1_kernel(const float* __restrict__ a1) {
    int t = blockIdx.x * blockDim.x + threadIdx.x;
    int w = t >> 5, lane = t & 31;
    if (w >= N_NODES*H1) return;
    int n = w / H1, h = w % H1;
    const float* p = g_proj1 + (size_t)n*C1 + h*F1;
    float v0 = p[lane], v1 = p[lane + 32];
    const float* av = a1 + h*2*F1;
    float s  = v0*av[lane]      + v1*av[lane + 32];
    float tn = v0*av[F1 + lane] + v1*av[F1 + lane + 32];
#pragma unroll
    for (int o = 16; o; o >>= 1) {
        s  += __shfl_xor_sync(FULL, s, o);
        tn += __shfl_xor_sync(FULL, tn, o);
    }
    if (!lane) { g_as1[w] = s; g_an1[w] = tn; }
}

// ---------------- combine split-K partials + attention (layer 2) -------------
__global__ void alpha2_combine(const float* __restrict__ a2) {
    int t = blockIdx.x * blockDim.x + threadIdx.x;
    int w = t >> 5, lane = t & 31;
    if (w >= N_NODES) return;
    const size_t NF = (size_t)N_NODES * F2;
    size_t base = (size_t)w*F2;
    float v0 = g_p2part[base + lane]        + g_p2part[NF + base + lane]
             + g_p2part[2*NF + base + lane] + g_p2part[3*NF + base + lane];
    float v1 = g_p2part[base + lane + 32]        + g_p2part[NF + base + lane + 32]
             + g_p2part[2*NF + base + lane + 32] + g_p2part[3*NF + base + lane + 32];
    g_proj2[base + lane] = v0;
    g_proj2[base + lane + 32] = v1;
    float s  = v0*a2[lane]      + v1*a2[lane + 32];
    float tn = v0*a2[F2 + lane] + v1*a2[F2 + lane + 32];
#pragma unroll
    for (int o = 16; o; o >>= 1) {
        s  += __shfl_xor_sync(FULL, s, o);
        tn += __shfl_xor_sync(FULL, tn, o);
    }
    if (!lane) { g_as2[w] = s; g_an2[w] = tn; }
}

// ---------------- fused gather: softmax + weighted agg + ELU (layer 1) -------
// one warp per (node, head); chunk-shuffle pattern for high MLP
__global__ void gather1() {
    int t = blockIdx.x * blockDim.x + threadIdx.x;
    int w = t >> 5, lane = t & 31;
    if (w >= N_NODES*H1) return;
    int n = w >> 3, h = w & 7;
    int beg = g_rowptr[n], end = g_rowptr[n + 1];
    float as = g_as1[n*H1 + h];

    // pass 1: segment max (lane-parallel)
    float mx = -3.0e38f;
    for (int i = beg + lane; i < end; i += 32) {
        float v = as + g_an1[g_nbr[i]*H1 + h];
        v = (v >= 0.f) ? v : NEG_SLOPE*v;
        mx = fmaxf(mx, v);
    }
#pragma unroll
    for (int o = 16; o; o >>= 1) mx = fmaxf(mx, __shfl_xor_sync(FULL, mx, o));

    // pass 2: lane-parallel weights, shuffle-broadcast feature accumulation
    float acc0 = 0.f, acc1 = 0.f, den = 0.f;
    const float* projh = g_proj1 + h*F1 + lane*2;
    for (int base = beg; base < end; base += 32) {
        int i = base + lane;
        int s = 0; float wgt = 0.f;
        if (i < end) {
            s = g_nbr[i];
            float v = as + g_an1[s*H1 + h];
            v = (v >= 0.f) ? v : NEG_SLOPE*v;
            wgt = __expf(v - mx);
            den += wgt;
        }
        int cnt = min(32, end - base);
        if (cnt == 32) {
#pragma unroll
            for (int j = 0; j < 32; j++) {
                float ww = __shfl_sync(FULL, wgt, j);
                int ss = __shfl_sync(FULL, s, j);
                float2 p = *(const float2*)&projh[(size_t)ss*C1];
                acc0 += ww * p.x;
                acc1 += ww * p.y;
            }
        } else {
#pragma unroll 4
            for (int j = 0; j < cnt; j++) {
                float ww = __shfl_sync(FULL, wgt, j);
                int ss = __shfl_sync(FULL, s, j);
                float2 p = *(const float2*)&projh[(size_t)ss*C1];
                acc0 += ww * p.x;
                acc1 += ww * p.y;
            }
        }
    }
#pragma unroll
    for (int o = 16; o; o >>= 1) den += __shfl_xor_sync(FULL, den, o);
    float inv = 1.f / den;
    acc0 *= inv; acc1 *= inv;
    acc0 = (acc0 > 0.f) ? acc0 : expm1f(acc0);   // ELU fused
    acc1 = (acc1 > 0.f) ? acc1 : expm1f(acc1);
    *(float2*)&g_hbuf[(size_t)n*C1 + h*F1 + lane*2] = make_float2(acc0, acc1);
}

// ---------------- fused gather layer 2 (H2=1, mean == identity) --------------
__global__ void gather2(float* __restrict__ out) {
    int t = blockIdx.x * blockDim.x + threadIdx.x;
    int w = t >> 5, lane = t & 31;
    if (w >= N_NODES) return;
    int n = w;
    int beg = g_rowptr[n], end = g_rowptr[n + 1];
    float as = g_as2[n];

    float mx = -3.0e38f;
    for (int i = beg + lane; i < end; i += 32) {
        float v = as + g_an2[g_nbr[i]];
        v = (v >= 0.f) ? v : NEG_SLOPE*v;
        mx = fmaxf(mx, v);
    }
#pragma unroll
    for (int o = 16; o; o >>= 1) mx = fmaxf(mx, __shfl_xor_sync(FULL, mx, o));

    float acc0 = 0.f, acc1 = 0.f, den = 0.f;
    const float* projl = g_proj2 + lane*2;
    for (int base = beg; base < end; base += 32) {
        int i = base + lane;
        int s = 0; float wgt = 0.f;
        if (i < end) {
            s = g_nbr[i];
            float v = as + g_an2[s];
            v = (v >= 0.f) ? v : NEG_SLOPE*v;
            wgt = __expf(v - mx);
            den += wgt;
        }
        int cnt = min(32, end - base);
        if (cnt == 32) {
#pragma unroll
            for (int j = 0; j < 32; j++) {
                float ww = __shfl_sync(FULL, wgt, j);
                int ss = __shfl_sync(FULL, s, j);
                float2 p = *(const float2*)&projl[(size_t)ss*F2];
                acc0 += ww * p.x;
                acc1 += ww * p.y;
            }
        } else {
#pragma unroll 4
            for (int j = 0; j < cnt; j++) {
                float ww = __shfl_sync(FULL, wgt, j);
                int ss = __shfl_sync(FULL, s, j);
                float2 p = *(const float2*)&projl[(size_t)ss*F2];
                acc0 += ww * p.x;
                acc1 += ww * p.y;
            }
        }
    }
#pragma unroll
    for (int o = 16; o; o >>= 1) den += __shfl_xor_sync(FULL, den, o);
    float inv = 1.f / den;
    *(float2*)&out[(size_t)n*F2 + lane*2] = make_float2(acc0*inv, acc1*inv);
}

// ---------------- launch -------------------------------------------------------
extern "C" void kernel_launch(void* const* d_in, const int* in_sizes, int n_in,
                              void* d_out, int out_size) {
    const float* x     = (const float*)d_in[0];
    const int*   edges = (const int*)d_in[1];
    const float* W1    = (const float*)d_in[2];
    const float* a1    = (const float*)d_in[3];
    const float* W2    = (const float*)d_in[4];
    const float* a2    = (const float*)d_in[5];
    float* out = (float*)d_out;

    void* cnt_ptr = nullptr; void* cur_ptr = nullptr;
    cudaGetSymbolAddress(&cnt_ptr, g_cnt);
    cudaGetSymbolAddress(&cur_ptr, g_cursor);
    cudaMemsetAsync(cnt_ptr, 0, N_NODES*sizeof(int));
    cudaMemsetAsync(cur_ptr, 0, N_NODES*sizeof(int));

    // graph prep
    build_edges<<<(NE + 255)/256, 256>>>(edges);
    scan_kernel<<<1, 1024>>>();
    fill_csr<<<(NE + 255)/256, 256>>>();
    repack_w1<<<(DIN*C1 + 255)/256, 256>>>(W1);

    // layer 1
    gemm1_kernel<<<dim3(C1/128, (N_NODES + 127)/128), 256>>>(x);
    alpha1_kernel<<<(N_NODES*H1*32 + 255)/256, 256>>>(a1);
    gather1<<<(N_NODES*H1*32 + 255)/256, 256>>>();

    // layer 2
    gemm2_kernel<<<dim3(1, (N_NODES + 63)/64, 4), 256>>>(W2);
    alpha2_combine<<<(N_NODES*32 + 255)/256, 256>>>(a2);
    gather2<<<(N_NODES*32 + 255)/256, 256>>>(out);
}

// round 5
// speedup vs baseline: 1.7701x; 1.0372x over previous
#include <cuda_runtime.h>
#include <cstdint>

#define N_NODES 10000
#define DIN 128
#define H1 8
#define F1 64
#define C1 512            // H1*F1
#define E0 80000
#define NE (2*E0 + N_NODES)   // 170000
#define F2 64
#define NEG_SLOPE 0.2f
#define FULL 0xffffffffu

// ---------------- scratch (static device globals; no allocation) -------------
static __device__ int   g_src[NE];
static __device__ int   g_dst[NE];
static __device__ int   g_cnt[N_NODES];
static __device__ int   g_cursor[N_NODES];
static __device__ int   g_rowptr[N_NODES + 1];
static __device__ int   g_nbr[NE];                 // CSR by dst: src indices
static __device__ float g_B1[DIN*C1];              // repacked W1 -> (K, H*F1)
static __device__ float g_proj1[N_NODES*C1];
static __device__ float g_as1[N_NODES*H1];
static __device__ float g_an1[N_NODES*H1];
static __device__ float g_hbuf[N_NODES*C1];        // layer-1 output (post ELU)
static __device__ float g_p2part[4*N_NODES*F2];    // split-K partials for gemm2
static __device__ float g_proj2[N_NODES*F2];
static __device__ float g_as2[N_NODES];
static __device__ float g_an2[N_NODES];

// ---------------- prep: edge decode + degree count + W1 repack ---------------
// Dtype probe: if edges are int64 LE with values < 2^31, odd 32-bit words are 0.
__global__ void prep_kernel(const int* __restrict__ e32,
                            const float* __restrict__ W1) {
    int i = blockIdx.x * blockDim.x + threadIdx.x;
    if (i < NE) {
        bool is64 = (e32[1] == 0) && (e32[3] == 0) && (e32[5] == 0) && (e32[7] == 0);
        int s, d;
        if (i < NE - N_NODES) {
            int j  = (i < E0) ? i : (i - E0);
            int si = (i < E0) ? j : (E0 + j);
            int di = (i < E0) ? (E0 + j) : j;
            s = is64 ? e32[2*si] : e32[si];
            d = is64 ? e32[2*di] : e32[di];
        } else {
            s = i - (NE - N_NODES); d = s;
        }
        s = min(max(s, 0), N_NODES - 1);
        d = min(max(d, 0), N_NODES - 1);
        g_src[i] = s; g_dst[i] = d;
        atomicAdd(&g_cnt[d], 1);
    }
    // repack W1 (H,Din,F1) -> (Din, H*F1); DIN*C1 = 65536 < NE
    if (i < DIN*C1) {
        int dd = i / C1, c = i % C1;
        int h = c >> 6, f = c & 63;
        g_B1[i] = W1[(h*DIN + dd)*F1 + f];
    }
}

// ---------------- exclusive scan of in-degrees (single block) ----------------
__global__ void scan_kernel() {
    __shared__ int ssum[1024];
    const int t = threadIdx.x;
    const int per = (N_NODES + 1023) / 1024;   // 10
    int base = t * per;
    int loc[16];
    int s = 0;
#pragma unroll
    for (int i = 0; i < per; i++) {
        int idx = base + i;
        int v = (idx < N_NODES) ? g_cnt[idx] : 0;
        loc[i] = v; s += v;
    }
    ssum[t] = s;
    __syncthreads();
    for (int off = 1; off < 1024; off <<= 1) {
        int v = (t >= off) ? ssum[t - off] : 0;
        __syncthreads();
        ssum[t] += v;
        __syncthreads();
    }
    int run = (t > 0) ? ssum[t - 1] : 0;
#pragma unroll
    for (int i = 0; i < per; i++) {
        int idx = base + i;
        if (idx < N_NODES) { g_rowptr[idx] = run; run += loc[i]; }
    }
    if (t == 1023) g_rowptr[N_NODES] = NE;
}

__global__ void fill_csr() {
    int e = blockIdx.x * blockDim.x + threadIdx.x;
    if (e >= NE) return;
    int d = g_dst[e];
    int slot = atomicAdd(&g_cursor[d], 1);
    g_nbr[g_rowptr[d] + slot] = g_src[e];
}

// ---------------- GEMM1: 128x128 tile, 8x8/thread ----------------------------
__global__ __launch_bounds__(256) void gemm1_kernel(const float* __restrict__ A) {
    __shared__ __align__(16) float As[8][132];
    __shared__ __align__(16) float Bs[8][128];
    const int tid = threadIdx.x;
    const int tx = tid & 15, ty = tid >> 4;
    const int row0 = blockIdx.y * 128;
    const int col0 = blockIdx.x * 128;
    const int M = N_NODES, N = C1, K = DIN;

    float acc[8][8];
#pragma unroll
    for (int i = 0; i < 8; i++)
#pragma unroll
        for (int j = 0; j < 8; j++) acc[i][j] = 0.f;

    const int ar = tid >> 1;
    const int akq = (tid & 1) * 4;
    const int bk = tid >> 5;
    const int bc = (tid & 31) * 4;

    for (int k0 = 0; k0 < K; k0 += 8) {
        int gr = row0 + ar;
        float4 va = (gr < M) ? *(const float4*)&A[(size_t)gr*K + k0 + akq]
                             : make_float4(0.f, 0.f, 0.f, 0.f);
        As[akq + 0][ar] = va.x;
        As[akq + 1][ar] = va.y;
        As[akq + 2][ar] = va.z;
        As[akq + 3][ar] = va.w;
        *(float4*)&Bs[bk][bc] = *(const float4*)&g_B1[(size_t)(k0 + bk)*N + col0 + bc];
        __syncthreads();
#pragma unroll
        for (int k = 0; k < 8; k++) {
            float4 a0 = *(const float4*)&As[k][ty*8];
            float4 a1 = *(const float4*)&As[k][ty*8 + 4];
            float4 b0 = *(const float4*)&Bs[k][tx*8];
            float4 b1 = *(const float4*)&Bs[k][tx*8 + 4];
            float a[8] = {a0.x,a0.y,a0.z,a0.w,a1.x,a1.y,a1.z,a1.w};
            float b[8] = {b0.x,b0.y,b0.z,b0.w,b1.x,b1.y,b1.z,b1.w};
#pragma unroll
            for (int i = 0; i < 8; i++)
#pragma unroll
                for (int j = 0; j < 8; j++) acc[i][j] += a[i]*b[j];
        }
        __syncthreads();
    }
#pragma unroll
    for (int i = 0; i < 8; i++) {
        int gr = row0 + ty*8 + i;
        if (gr < M) {
            *(float4*)&g_proj1[(size_t)gr*N + col0 + tx*8]     =
                make_float4(acc[i][0], acc[i][1], acc[i][2], acc[i][3]);
            *(float4*)&g_proj1[(size_t)gr*N + col0 + tx*8 + 4] =
                make_float4(acc[i][4], acc[i][5], acc[i][6], acc[i][7]);
        }
    }
}

// ---------------- GEMM2 split-K: 64x64 tile, K-chunk 128 per z ---------------
__global__ void gemm2_kernel(const float* __restrict__ B) {
    __shared__ __align__(16) float As[16][68];
    __shared__ __align__(16) float Bs[16][64];
    const float* A = g_hbuf;
    const int M = N_NODES, N = F2, K = C1;
    const int tid = threadIdx.x;
    const int tx = tid & 15, ty = tid >> 4;
    const int row0 = blockIdx.y * 64;
    const int kz0 = blockIdx.z * (K/4);
    float* C = g_p2part + (size_t)blockIdx.z * N_NODES * F2;
    float acc[4][4];
#pragma unroll
    for (int i = 0; i < 4; i++)
#pragma unroll
        for (int j = 0; j < 4; j++) acc[i][j] = 0.f;

    for (int k0 = kz0; k0 < kz0 + K/4; k0 += 16) {
#pragma unroll
        for (int l = 0; l < 4; l++) {
            int i = tid + l*256;
            int r = i >> 4, kk = i & 15;
            int gr = row0 + r;
            As[kk][r] = (gr < M) ? A[(size_t)gr*K + k0 + kk] : 0.f;
        }
        {
            int kk = tid >> 6, c = tid & 63;
            Bs[kk][c]      = B[(size_t)(k0 + kk)*N + c];
            Bs[kk + 4][c]  = B[(size_t)(k0 + kk + 4)*N + c];
            Bs[kk + 8][c]  = B[(size_t)(k0 + kk + 8)*N + c];
            Bs[kk + 12][c] = B[(size_t)(k0 + kk + 12)*N + c];
        }
        __syncthreads();
#pragma unroll
        for (int kk = 0; kk < 16; kk++) {
            float4 av = *(const float4*)&As[kk][ty*4];
            float4 bv = *(const float4*)&Bs[kk][tx*4];
            float a[4] = {av.x, av.y, av.z, av.w};
            float b[4] = {bv.x, bv.y, bv.z, bv.w};
#pragma unroll
            for (int i = 0; i < 4; i++)
#pragma unroll
                for (int j = 0; j < 4; j++) acc[i][j] += a[i]*b[j];
        }
        __syncthreads();
    }
#pragma unroll
    for (int i = 0; i < 4; i++) {
        int gr = row0 + ty*4 + i;
        if (gr < M) {
            *(float4*)&C[(size_t)gr*N + tx*4] =
                make_float4(acc[i][0], acc[i][1], acc[i][2], acc[i][3]);
        }
    }
}

// ---------------- attention coefficients (layer 1) ---------------------------
__global__ void alpha1_kernel(const float* __restrict__ a1) {
    int t = blockIdx.x * blockDim.x + threadIdx.x;
    int w = t >> 5, lane = t & 31;
    if (w >= N_NODES*H1) return;
    int n = w / H1, h = w % H1;
    const float* p = g_proj1 + (size_t)n*C1 + h*F1;
    float v0 = p[lane], v1 = p[lane + 32];
    const float* av = a1 + h*2*F1;
    float s  = v0*av[lane]      + v1*av[lane + 32];
    float tn = v0*av[F1 + lane] + v1*av[F1 + lane + 32];
#pragma unroll
    for (int o = 16; o; o >>= 1) {
        s  += __shfl_xor_sync(FULL, s, o);
        tn += __shfl_xor_sync(FULL, tn, o);
    }
    if (!lane) { g_as1[w] = s; g_an1[w] = tn; }
}

// ---------------- combine split-K partials + attention (layer 2) -------------
__global__ void alpha2_combine(const float* __restrict__ a2) {
    int t = blockIdx.x * blockDim.x + threadIdx.x;
    int w = t >> 5, lane = t & 31;
    if (w >= N_NODES) return;
    const size_t NF = (size_t)N_NODES * F2;
    size_t base = (size_t)w*F2;
    float v0 = g_p2part[base + lane]        + g_p2part[NF + base + lane]
             + g_p2part[2*NF + base + lane] + g_p2part[3*NF + base + lane];
    float v1 = g_p2part[base + lane + 32]        + g_p2part[NF + base + lane + 32]
             + g_p2part[2*NF + base + lane + 32] + g_p2part[3*NF + base + lane + 32];
    g_proj2[base + lane] = v0;
    g_proj2[base + lane + 32] = v1;
    float s  = v0*a2[lane]      + v1*a2[lane + 32];
    float tn = v0*a2[F2 + lane] + v1*a2[F2 + lane + 32];
#pragma unroll
    for (int o = 16; o; o >>= 1) {
        s  += __shfl_xor_sync(FULL, s, o);
        tn += __shfl_xor_sync(FULL, tn, o);
    }
    if (!lane) { g_as2[w] = s; g_an2[w] = tn; }
}

// ---------------- fused gather: softmax + weighted agg + ELU (layer 1) -------
// one warp per (node, head); 2 edges/iter, 16 feature-lanes each, LDG.128
__global__ void gather1() {
    int t = blockIdx.x * blockDim.x + threadIdx.x;
    int w = t >> 5, lane = t & 31;
    if (w >= N_NODES*H1) return;
    int n = w >> 3, h = w & 7;
    int beg = g_rowptr[n], end = g_rowptr[n + 1];
    float as = g_as1[n*H1 + h];

    // pass 1: segment max (lane-parallel)
    float mx = -3.0e38f;
    for (int i = beg + lane; i < end; i += 32) {
        float v = as + g_an1[g_nbr[i]*H1 + h];
        v = (v >= 0.f) ? v : NEG_SLOPE*v;
        mx = fmaxf(mx, v);
    }
#pragma unroll
    for (int o = 16; o; o >>= 1) mx = fmaxf(mx, __shfl_xor_sync(FULL, mx, o));

    // pass 2: lane-parallel weights; features via 2-edges-per-iter LDG.128
    const int half = lane >> 4;            // 0: even edge, 1: odd edge
    const int fl = (lane & 15) * 4;        // feature offset (0..60)
    const float* projh = g_proj1 + h*F1 + fl;
    float a0 = 0.f, a1v = 0.f, a2v = 0.f, a3 = 0.f, den = 0.f;
    for (int base = beg; base < end; base += 32) {
        int i = base + lane;
        int s = 0; float wgt = 0.f;
        if (i < end) {
            s = g_nbr[i];
            float v = as + g_an1[s*H1 + h];
            v = (v >= 0.f) ? v : NEG_SLOPE*v;
            wgt = __expf(v - mx);
            den += wgt;
        }
        int cnt = min(32, end - base);
        if (cnt == 32) {
#pragma unroll
            for (int j = 0; j < 16; j++) {
                int sl = 2*j + half;
                float ww = __shfl_sync(FULL, wgt, sl);
                int ss = __shfl_sync(FULL, s, sl);
                float4 p = *(const float4*)&projh[(size_t)ss*C1];
                a0 += ww*p.x; a1v += ww*p.y; a2v += ww*p.z; a3 += ww*p.w;
            }
        } else {
            int jmax = (cnt + 1) >> 1;
            for (int j = 0; j < jmax; j++) {
                int sl = 2*j + half;                 // wgt=0 beyond cnt -> safe
                float ww = __shfl_sync(FULL, wgt, sl);
                int ss = __shfl_sync(FULL, s, sl);
                float4 p = *(const float4*)&projh[(size_t)ss*C1];
                a0 += ww*p.x; a1v += ww*p.y; a2v += ww*p.z; a3 += ww*p.w;
            }
        }
    }
    // fold the two edge-halves together, reduce den across warp
    a0  += __shfl_xor_sync(FULL, a0, 16);
    a1v += __shfl_xor_sync(FULL, a1v, 16);
    a2v += __shfl_xor_sync(FULL, a2v, 16);
    a3  += __shfl_xor_sync(FULL, a3, 16);
#pragma unroll
    for (int o = 16; o; o >>= 1) den += __shfl_xor_sync(FULL, den, o);
    if (lane < 16) {
        float inv = 1.f / den;
        a0 *= inv; a1v *= inv; a2v *= inv; a3 *= inv;
        a0  = (a0  > 0.f) ? a0  : expm1f(a0);
        a1v = (a1v > 0.f) ? a1v : expm1f(a1v);
        a2v = (a2v > 0.f) ? a2v : expm1f(a2v);
        a3  = (a3  > 0.f) ? a3  : expm1f(a3);
        *(float4*)&g_hbuf[(size_t)n*C1 + h*F1 + fl] = make_float4(a0, a1v, a2v, a3);
    }
}

// ---------------- fused gather layer 2 (H2=1, mean == identity) --------------
__global__ void gather2(float* __restrict__ out) {
    int t = blockIdx.x * blockDim.x + threadIdx.x;
    int w = t >> 5, lane = t & 31;
    if (w >= N_NODES) return;
    int n = w;
    int beg = g_rowptr[n], end = g_rowptr[n + 1];
    float as = g_as2[n];

    float mx = -3.0e38f;
    for (int i = beg + lane; i < end; i += 32) {
        float v = as + g_an2[g_nbr[i]];
        v = (v >= 0.f) ? v : NEG_SLOPE*v;
        mx = fmaxf(mx, v);
    }
#pragma unroll
    for (int o = 16; o; o >>= 1) mx = fmaxf(mx, __shfl_xor_sync(FULL, mx, o));

    const int half = lane >> 4;
    const int fl = (lane & 15) * 4;
    const float* projl = g_proj2 + fl;
    float a0 = 0.f, a1v = 0.f, a2v = 0.f, a3 = 0.f, den = 0.f;
    for (int base = beg; base < end; base += 32) {
        int i = base + lane;
        int s = 0; float wgt = 0.f;
        if (i < end) {
            s = g_nbr[i];
            float v = as + g_an2[s];
            v = (v >= 0.f) ? v : NEG_SLOPE*v;
            wgt = __expf(v - mx);
            den += wgt;
        }
        int cnt = min(32, end - base);
        if (cnt == 32) {
#pragma unroll
            for (int j = 0; j < 16; j++) {
                int sl = 2*j + half;
                float ww = __shfl_sync(FULL, wgt, sl);
                int ss = __shfl_sync(FULL, s, sl);
                float4 p = *(const float4*)&projl[(size_t)ss*F2];
                a0 += ww*p.x; a1v += ww*p.y; a2v += ww*p.z; a3 += ww*p.w;
            }
        } else {
            int jmax = (cnt + 1) >> 1;
            for (int j = 0; j < jmax; j++) {
                int sl = 2*j + half;
                float ww = __shfl_sync(FULL, wgt, sl);
                int ss = __shfl_sync(FULL, s, sl);
                float4 p = *(const float4*)&projl[(size_t)ss*F2];
                a0 += ww*p.x; a1v += ww*p.y; a2v += ww*p.z; a3 += ww*p.w;
            }
        }
    }
    a0  += __shfl_xor_sync(FULL, a0, 16);
    a1v += __shfl_xor_sync(FULL, a1v, 16);
    a2v += __shfl_xor_sync(FULL, a2v, 16);
    a3  += __shfl_xor_sync(FULL, a3, 16);
#pragma unroll
    for (int o = 16; o; o >>= 1) den += __shfl_xor_sync(FULL, den, o);
    if (lane < 16) {
        float inv = 1.f / den;
        *(float4*)&out[(size_t)n*F2 + fl] =
            make_float4(a0*inv, a1v*inv, a2v*inv, a3*inv);
    }
}

// ---------------- launch -------------------------------------------------------
extern "C" void kernel_launch(void* const* d_in, const int* in_sizes, int n_in,
                              void* d_out, int out_size) {
    const float* x     = (const float*)d_in[0];
    const int*   edges = (const int*)d_in[1];
    const float* W1    = (const float*)d_in[2];
    const float* a1    = (const float*)d_in[3];
    const float* W2    = (const float*)d_in[4];
    const float* a2    = (const float*)d_in[5];
    float* out = (float*)d_out;

    void* cnt_ptr = nullptr; void* cur_ptr = nullptr;
    cudaGetSymbolAddress(&cnt_ptr, g_cnt);
    cudaGetSymbolAddress(&cur_ptr, g_cursor);
    cudaMemsetAsync(cnt_ptr, 0, N_NODES*sizeof(int));      // launch 1
    cudaMemsetAsync(cur_ptr, 0, N_NODES*sizeof(int));      // launch 2

    prep_kernel<<<(NE + 255)/256, 256>>>(edges, W1);       // launch 3
    scan_kernel<<<1, 1024>>>();                            // launch 4
    fill_csr<<<(NE + 255)/256, 256>>>();                   // launch 5

    // layer 1  (gemm1 = launch 6 -> ncu profile slot)
    gemm1_kernel<<<dim3(C1/128, (N_NODES + 127)/128), 256>>>(x);
    alpha1_kernel<<<(N_NODES*H1*32 + 255)/256, 256>>>(a1);
    gather1<<<(N_NODES*H1*32 + 255)/256, 256>>>();

    // layer 2
    gemm2_kernel<<<dim3(1, (N_NODES + 63)/64, 4), 256>>>(W2);
    alpha2_combine<<<(N_NODES*32 + 255)/256, 256>>>(a2);
    gather2<<<(N_NODES*32 + 255)/256, 256>>>(out);
}

// round 6
// speedup vs baseline: 1.9665x; 1.1110x over previous
#include <cuda_runtime.h>
#include <cstdint>

#define N_NODES 10000
#define DIN 128
#define H1 8
#define F1 64
#define C1 512            // H1*F1
#define E0 80000
#define NE (2*E0 + N_NODES)   // 170000
#define F2 64
#define NEG_SLOPE 0.2f
#define FULL 0xffffffffu

// ---------------- scratch (static device globals; no allocation) -------------
static __device__ int   g_src[NE];
static __device__ int   g_dst[NE];
static __device__ int   g_cnt[N_NODES];
static __device__ int   g_cursor[N_NODES];
static __device__ int   g_rowptr[N_NODES + 1];
static __device__ int   g_nbr[NE];                 // CSR by dst: src indices
static __device__ float g_B1[DIN*C1];              // repacked W1 -> (K, H*F1)
static __device__ float g_proj1[N_NODES*C1];
static __device__ float g_as1[N_NODES*H1];
static __device__ float g_an1[N_NODES*H1];
static __device__ float g_hbuf[N_NODES*C1];        // layer-1 output (post ELU)
static __device__ float g_p2part[4*N_NODES*F2];    // split-K partials for gemm2
static __device__ float g_proj2[N_NODES*F2];
static __device__ float g_as2[N_NODES];
static __device__ float g_an2[N_NODES];

// ---------------- prep: edge decode + degree count + W1 repack ---------------
// Dtype probe: if edges are int64 LE with values < 2^31, odd 32-bit words are 0.
__global__ void prep_kernel(const int* __restrict__ e32,
                            const float* __restrict__ W1) {
    int i = blockIdx.x * blockDim.x + threadIdx.x;
    if (i < NE) {
        bool is64 = (e32[1] == 0) && (e32[3] == 0) && (e32[5] == 0) && (e32[7] == 0);
        int s, d;
        if (i < NE - N_NODES) {
            int j  = (i < E0) ? i : (i - E0);
            int si = (i < E0) ? j : (E0 + j);
            int di = (i < E0) ? (E0 + j) : j;
            s = is64 ? e32[2*si] : e32[si];
            d = is64 ? e32[2*di] : e32[di];
        } else {
            s = i - (NE - N_NODES); d = s;
        }
        s = min(max(s, 0), N_NODES - 1);
        d = min(max(d, 0), N_NODES - 1);
        g_src[i] = s; g_dst[i] = d;
        atomicAdd(&g_cnt[d], 1);
    }
    // repack W1 (H,Din,F1) -> (Din, H*F1); DIN*C1 = 65536 < NE
    if (i < DIN*C1) {
        int dd = i / C1, c = i % C1;
        int h = c >> 6, f = c & 63;
        g_B1[i] = W1[(h*DIN + dd)*F1 + f];
    }
}

// ---------------- exclusive scan of in-degrees (single block) ----------------
__global__ void scan_kernel() {
    __shared__ int ssum[1024];
    const int t = threadIdx.x;
    const int per = (N_NODES + 1023) / 1024;   // 10
    int base = t * per;
    int loc[16];
    int s = 0;
#pragma unroll
    for (int i = 0; i < per; i++) {
        int idx = base + i;
        int v = (idx < N_NODES) ? g_cnt[idx] : 0;
        loc[i] = v; s += v;
    }
    ssum[t] = s;
    __syncthreads();
    for (int off = 1; off < 1024; off <<= 1) {
        int v = (t >= off) ? ssum[t - off] : 0;
        __syncthreads();
        ssum[t] += v;
        __syncthreads();
    }
    int run = (t > 0) ? ssum[t - 1] : 0;
#pragma unroll
    for (int i = 0; i < per; i++) {
        int idx = base + i;
        if (idx < N_NODES) { g_rowptr[idx] = run; run += loc[i]; }
    }
    if (t == 1023) g_rowptr[N_NODES] = NE;
}

__global__ void fill_csr() {
    int e = blockIdx.x * blockDim.x + threadIdx.x;
    if (e >= NE) return;
    int d = g_dst[e];
    int slot = atomicAdd(&g_cursor[d], 1);
    g_nbr[g_rowptr[d] + slot] = g_src[e];
}

// ---------------- GEMM1: 64x64 tile, 4x4/thread, double-buffered -------------
// Fused alpha1 epilogue: blockIdx.x == head index (tile width 64 == F1).
__global__ __launch_bounds__(256) void gemm1_kernel(const float* __restrict__ A,
                                                    const float* __restrict__ a1) {
    __shared__ __align__(16) float As[2][16][68];
    __shared__ __align__(16) float Bs[2][16][64];
    const int tid = threadIdx.x;
    const int tx = tid & 15, ty = tid >> 4;
    const int row0 = blockIdx.y * 64;
    const int col0 = blockIdx.x * 64;
    const int M = N_NODES, N = C1, K = DIN;

    // load indices (constant across iterations)
    const int akk = tid & 15;          // A k within tile
    const int ar0 = tid >> 4;          // A row base (adds l*16)
    const int bc  = tid & 63;          // B col
    const int bk0 = tid >> 6;          // B k base (adds l*4)

    float acc[4][4];
#pragma unroll
    for (int i = 0; i < 4; i++)
#pragma unroll
        for (int j = 0; j < 4; j++) acc[i][j] = 0.f;

    // preload tile 0
#pragma unroll
    for (int l = 0; l < 4; l++) {
        int gr = row0 + ar0 + l*16;
        As[0][akk][ar0 + l*16] = (gr < M) ? A[(size_t)gr*K + akk] : 0.f;
        Bs[0][bk0 + l*4][bc]   = g_B1[(size_t)(bk0 + l*4)*N + col0 + bc];
    }
    __syncthreads();

    const int nIter = K / 16;          // 8
    int p = 0;
    for (int it = 0; it < nIter; it++) {
        float ra[4], rb[4];
        if (it + 1 < nIter) {
            int k0 = (it + 1) * 16;
#pragma unroll
            for (int l = 0; l < 4; l++) {
                int gr = row0 + ar0 + l*16;
                ra[l] = (gr < M) ? A[(size_t)gr*K + k0 + akk] : 0.f;
                rb[l] = g_B1[(size_t)(k0 + bk0 + l*4)*N + col0 + bc];
            }
        }
#pragma unroll
        for (int kk = 0; kk < 16; kk++) {
            float4 av = *(const float4*)&As[p][kk][ty*4];
            float4 bv = *(const float4*)&Bs[p][kk][tx*4];
            float a[4] = {av.x, av.y, av.z, av.w};
            float b[4] = {bv.x, bv.y, bv.z, bv.w};
#pragma unroll
            for (int i = 0; i < 4; i++)
#pragma unroll
                for (int j = 0; j < 4; j++) acc[i][j] += a[i]*b[j];
        }
        if (it + 1 < nIter) {
#pragma unroll
            for (int l = 0; l < 4; l++) {
                As[p^1][akk][ar0 + l*16] = ra[l];
                Bs[p^1][bk0 + l*4][bc]   = rb[l];
            }
            __syncthreads();
            p ^= 1;
        }
    }

    // store C tile
#pragma unroll
    for (int i = 0; i < 4; i++) {
        int gr = row0 + ty*4 + i;
        if (gr < M) {
            *(float4*)&g_proj1[(size_t)gr*N + col0 + tx*4] =
                make_float4(acc[i][0], acc[i][1], acc[i][2], acc[i][3]);
        }
    }

    // fused alpha1: per-row dots with a_self / a_nb, reduce across 16 tx lanes
    const int h = blockIdx.x;          // head index
    float avs[4], avn[4];
#pragma unroll
    for (int j = 0; j < 4; j++) {
        avs[j] = __ldg(&a1[h*2*F1 + tx*4 + j]);
        avn[j] = __ldg(&a1[h*2*F1 + F1 + tx*4 + j]);
    }
#pragma unroll
    for (int i = 0; i < 4; i++) {
        float s = acc[i][0]*avs[0] + acc[i][1]*avs[1] + acc[i][2]*avs[2] + acc[i][3]*avs[3];
        float n = acc[i][0]*avn[0] + acc[i][1]*avn[1] + acc[i][2]*avn[2] + acc[i][3]*avn[3];
#pragma unroll
        for (int o = 8; o; o >>= 1) {
            s += __shfl_xor_sync(FULL, s, o);
            n += __shfl_xor_sync(FULL, n, o);
        }
        int gr = row0 + ty*4 + i;
        if (tx == 0 && gr < M) {
            g_as1[gr*H1 + h] = s;
            g_an1[gr*H1 + h] = n;
        }
    }
}

// ---------------- GEMM2 split-K: 64x64 tile, K-chunk 128 per z ---------------
__global__ void gemm2_kernel(const float* __restrict__ B) {
    __shared__ __align__(16) float As[16][68];
    __shared__ __align__(16) float Bs[16][64];
    const float* A = g_hbuf;
    const int M = N_NODES, N = F2, K = C1;
    const int tid = threadIdx.x;
    const int tx = tid & 15, ty = tid >> 4;
    const int row0 = blockIdx.y * 64;
    const int kz0 = blockIdx.z * (K/4);
    float* C = g_p2part + (size_t)blockIdx.z * N_NODES * F2;
    float acc[4][4];
#pragma unroll
    for (int i = 0; i < 4; i++)
#pragma unroll
        for (int j = 0; j < 4; j++) acc[i][j] = 0.f;

    for (int k0 = kz0; k0 < kz0 + K/4; k0 += 16) {
#pragma unroll
        for (int l = 0; l < 4; l++) {
            int i = tid + l*256;
            int r = i >> 4, kk = i & 15;
            int gr = row0 + r;
            As[kk][r] = (gr < M) ? A[(size_t)gr*K + k0 + kk] : 0.f;
        }
        {
            int kk = tid >> 6, c = tid & 63;
            Bs[kk][c]      = B[(size_t)(k0 + kk)*N + c];
            Bs[kk + 4][c]  = B[(size_t)(k0 + kk + 4)*N + c];
            Bs[kk + 8][c]  = B[(size_t)(k0 + kk + 8)*N + c];
            Bs[kk + 12][c] = B[(size_t)(k0 + kk + 12)*N + c];
        }
        __syncthreads();
#pragma unroll
        for (int kk = 0; kk < 16; kk++) {
            float4 av = *(const float4*)&As[kk][ty*4];
            float4 bv = *(const float4*)&Bs[kk][tx*4];
            float a[4] = {av.x, av.y, av.z, av.w};
            float b[4] = {bv.x, bv.y, bv.z, bv.w};
#pragma unroll
            for (int i = 0; i < 4; i++)
#pragma unroll
                for (int j = 0; j < 4; j++) acc[i][j] += a[i]*b[j];
        }
        __syncthreads();
    }
#pragma unroll
    for (int i = 0; i < 4; i++) {
        int gr = row0 + ty*4 + i;
        if (gr < M) {
            *(float4*)&C[(size_t)gr*N + tx*4] =
                make_float4(acc[i][0], acc[i][1], acc[i][2], acc[i][3]);
        }
    }
}

// ---------------- combine split-K partials + attention (layer 2) -------------
__global__ void alpha2_combine(const float* __restrict__ a2) {
    int t = blockIdx.x * blockDim.x + threadIdx.x;
    int w = t >> 5, lane = t & 31;
    if (w >= N_NODES) return;
    const size_t NF = (size_t)N_NODES * F2;
    size_t base = (size_t)w*F2;
    float v0 = g_p2part[base + lane]        + g_p2part[NF + base + lane]
             + g_p2part[2*NF + base + lane] + g_p2part[3*NF + base + lane];
    float v1 = g_p2part[base + lane + 32]        + g_p2part[NF + base + lane + 32]
             + g_p2part[2*NF + base + lane + 32] + g_p2part[3*NF + base + lane + 32];
    g_proj2[base + lane] = v0;
    g_proj2[base + lane + 32] = v1;
    float s  = v0*a2[lane]      + v1*a2[lane + 32];
    float tn = v0*a2[F2 + lane] + v1*a2[F2 + lane + 32];
#pragma unroll
    for (int o = 16; o; o >>= 1) {
        s  += __shfl_xor_sync(FULL, s, o);
        tn += __shfl_xor_sync(FULL, tn, o);
    }
    if (!lane) { g_as2[w] = s; g_an2[w] = tn; }
}

// ---------------- fused gather: softmax + weighted agg + ELU (layer 1) -------
// one warp per (node, head); 2 edges/iter, 16 feature-lanes each, LDG.128
__global__ void gather1() {
    int t = blockIdx.x * blockDim.x + threadIdx.x;
    int w = t >> 5, lane = t & 31;
    if (w >= N_NODES*H1) return;
    int n = w >> 3, h = w & 7;
    int beg = g_rowptr[n], end = g_rowptr[n + 1];
    float as = g_as1[n*H1 + h];

    // pass 1: segment max (lane-parallel)
    float mx = -3.0e38f;
    for (int i = beg + lane; i < end; i += 32) {
        float v = as + g_an1[g_nbr[i]*H1 + h];
        v = (v >= 0.f) ? v : NEG_SLOPE*v;
        mx = fmaxf(mx, v);
    }
#pragma unroll
    for (int o = 16; o; o >>= 1) mx = fmaxf(mx, __shfl_xor_sync(FULL, mx, o));

    // pass 2: lane-parallel weights; features via 2-edges-per-iter LDG.128
    const int half = lane >> 4;            // 0: even edge, 1: odd edge
    const int fl = (lane & 15) * 4;        // feature offset (0..60)
    const float* projh = g_proj1 + h*F1 + fl;
    float a0 = 0.f, a1v = 0.f, a2v = 0.f, a3 = 0.f, den = 0.f;
    for (int base = beg; base < end; base += 32) {
        int i = base + lane;
        int s = 0; float wgt = 0.f;
        if (i < end) {
            s = g_nbr[i];
            float v = as + g_an1[s*H1 + h];
            v = (v >= 0.f) ? v : NEG_SLOPE*v;
            wgt = __expf(v - mx);
            den += wgt;
        }
        int cnt = min(32, end - base);
        if (cnt == 32) {
#pragma unroll
            for (int j = 0; j < 16; j++) {
                int sl = 2*j + half;
                float ww = __shfl_sync(FULL, wgt, sl);
                int ss = __shfl_sync(FULL, s, sl);
                float4 p = *(const float4*)&projh[(size_t)ss*C1];
                a0 += ww*p.x; a1v += ww*p.y; a2v += ww*p.z; a3 += ww*p.w;
            }
        } else {
            int jmax = (cnt + 1) >> 1;
            for (int j = 0; j < jmax; j++) {
                int sl = 2*j + half;                 // wgt=0 beyond cnt -> safe
                float ww = __shfl_sync(FULL, wgt, sl);
                int ss = __shfl_sync(FULL, s, sl);
                float4 p = *(const float4*)&projh[(size_t)ss*C1];
                a0 += ww*p.x; a1v += ww*p.y; a2v += ww*p.z; a3 += ww*p.w;
            }
        }
    }
    a0  += __shfl_xor_sync(FULL, a0, 16);
    a1v += __shfl_xor_sync(FULL, a1v, 16);
    a2v += __shfl_xor_sync(FULL, a2v, 16);
    a3  += __shfl_xor_sync(FULL, a3, 16);
#pragma unroll
    for (int o = 16; o; o >>= 1) den += __shfl_xor_sync(FULL, den, o);
    if (lane < 16) {
        float inv = 1.f / den;
        a0 *= inv; a1v *= inv; a2v *= inv; a3 *= inv;
        a0  = (a0  > 0.f) ? a0  : expm1f(a0);
        a1v = (a1v > 0.f) ? a1v : expm1f(a1v);
        a2v = (a2v > 0.f) ? a2v : expm1f(a2v);
        a3  = (a3  > 0.f) ? a3  : expm1f(a3);
        *(float4*)&g_hbuf[(size_t)n*C1 + h*F1 + fl] = make_float4(a0, a1v, a2v, a3);
    }
}

// ---------------- fused gather layer 2 (H2=1, mean == identity) --------------
__global__ void gather2(float* __restrict__ out) {
    int t = blockIdx.x * blockDim.x + threadIdx.x;
    int w = t >> 5, lane = t & 31;
    if (w >= N_NODES) return;
    int n = w;
    int beg = g_rowptr[n], end = g_rowptr[n + 1];
    float as = g_as2[n];

    float mx = -3.0e38f;
    for (int i = beg + lane; i < end; i += 32) {
        float v = as + g_an2[g_nbr[i]];
        v = (v >= 0.f) ? v : NEG_SLOPE*v;
        mx = fmaxf(mx, v);
    }
#pragma unroll
    for (int o = 16; o; o >>= 1) mx = fmaxf(mx, __shfl_xor_sync(FULL, mx, o));

    const int half = lane >> 4;
    const int fl = (lane & 15) * 4;
    const float* projl = g_proj2 + fl;
    float a0 = 0.f, a1v = 0.f, a2v = 0.f, a3 = 0.f, den = 0.f;
    for (int base = beg; base < end; base += 32) {
        int i = base + lane;
        int s = 0; float wgt = 0.f;
        if (i < end) {
            s = g_nbr[i];
            float v = as + g_an2[s];
            v = (v >= 0.f) ? v : NEG_SLOPE*v;
            wgt = __expf(v - mx);
            den += wgt;
        }
        int cnt = min(32, end - base);
        if (cnt == 32) {
#pragma unroll
            for (int j = 0; j < 16; j++) {
                int sl = 2*j + half;
                float ww = __shfl_sync(FULL, wgt, sl);
                int ss = __shfl_sync(FULL, s, sl);
                float4 p = *(const float4*)&projl[(size_t)ss*F2];
                a0 += ww*p.x; a1v += ww*p.y; a2v += ww*p.z; a3 += ww*p.w;
            }
        } else {
            int jmax = (cnt + 1) >> 1;
            for (int j = 0; j < jmax; j++) {
                int sl = 2*j + half;
                float ww = __shfl_sync(FULL, wgt, sl);
                int ss = __shfl_sync(FULL, s, sl);
                float4 p = *(const float4*)&projl[(size_t)ss*F2];
                a0 += ww*p.x; a1v += ww*p.y; a2v += ww*p.z; a3 += ww*p.w;
            }
        }
    }
    a0  += __shfl_xor_sync(FULL, a0, 16);
    a1v += __shfl_xor_sync(FULL, a1v, 16);
    a2v += __shfl_xor_sync(FULL, a2v, 16);
    a3  += __shfl_xor_sync(FULL, a3, 16);
#pragma unroll
    for (int o = 16; o; o >>= 1) den += __shfl_xor_sync(FULL, den, o);
    if (lane < 16) {
        float inv = 1.f / den;
        *(float4*)&out[(size_t)n*F2 + fl] =
            make_float4(a0*inv, a1v*inv, a2v*inv, a3*inv);
    }
}

// ---------------- launch -------------------------------------------------------
extern "C" void kernel_launch(void* const* d_in, const int* in_sizes, int n_in,
                              void* d_out, int out_size) {
    const float* x     = (const float*)d_in[0];
    const int*   edges = (const int*)d_in[1];
    const float* W1    = (const float*)d_in[2];
    const float* a1    = (const float*)d_in[3];
    const float* W2    = (const float*)d_in[4];
    const float* a2    = (const float*)d_in[5];
    float* out = (float*)d_out;

    void* cnt_ptr = nullptr; void* cur_ptr = nullptr;
    cudaGetSymbolAddress(&cnt_ptr, g_cnt);
    cudaGetSymbolAddress(&cur_ptr, g_cursor);
    cudaMemsetAsync(cnt_ptr, 0, N_NODES*sizeof(int));      // launch 1
    cudaMemsetAsync(cur_ptr, 0, N_NODES*sizeof(int));      // launch 2

    prep_kernel<<<(NE + 255)/256, 256>>>(edges, W1);       // launch 3
    scan_kernel<<<1, 1024>>>();                            // launch 4
    fill_csr<<<(NE + 255)/256, 256>>>();                   // launch 5

    // layer 1  (gemm1 = launch 6 -> ncu profile slot; alpha1 fused in epilogue)
    gemm1_kernel<<<dim3(C1/64, (N_NODES + 63)/64), 256>>>(x, a1);
    gather1<<<(N_NODES*H1*32 + 255)/256, 256>>>();

    // layer 2
    gemm2_kernel<<<dim3(1, (N_NODES + 63)/64, 4), 256>>>(W2);
    alpha2_combine<<<(N_NODES*32 + 255)/256, 256>>>(a2);
    gather2<<<(N_NODES*32 + 255)/256, 256>>>(out);
}

// round 7
// speedup vs baseline: 2.2108x; 1.1243x over previous
#include <cuda_runtime.h>
#include <cuda_bf16.h>
#include <cstdint>

#define N_NODES 10000
#define DIN 128
#define H1 8
#define F1 64
#define C1 512            // H1*F1
#define E0 80000
#define NE (2*E0 + N_NODES)   // 170000
#define F2 64
#define NEG_SLOPE 0.2f
#define FULL 0xffffffffu

// ---------------- scratch (static device globals; no allocation) -------------
static __device__ int   g_src[NE];
static __device__ int   g_dst[NE];
static __device__ int   g_cnt[N_NODES];
static __device__ int   g_cursor[N_NODES];
static __device__ int   g_rowptr[N_NODES + 1];
static __device__ int   g_nbr[NE];                 // CSR by dst: src indices
static __device__ float g_B1[DIN*C1];              // repacked W1 -> (K, H*F1)
static __device__ float g_proj1[N_NODES*C1];
static __device__ float g_as1[N_NODES*H1];
static __device__ float g_an1[N_NODES*H1];
static __device__ float g_hbuf[N_NODES*C1];        // layer-1 output (post ELU)
static __device__ float g_p2part[4*N_NODES*F2];    // split-K partials for gemm2
static __device__ float g_proj2[N_NODES*F2];
static __device__ float g_as2[N_NODES];
static __device__ float g_an2[N_NODES];

// ---------------- prep: edge decode + degree count + W1 repack ---------------
__global__ void prep_kernel(const int* __restrict__ e32,
                            const float* __restrict__ W1) {
    int i = blockIdx.x * blockDim.x + threadIdx.x;
    if (i < NE) {
        bool is64 = (e32[1] == 0) && (e32[3] == 0) && (e32[5] == 0) && (e32[7] == 0);
        int s, d;
        if (i < NE - N_NODES) {
            int j  = (i < E0) ? i : (i - E0);
            int si = (i < E0) ? j : (E0 + j);
            int di = (i < E0) ? (E0 + j) : j;
            s = is64 ? e32[2*si] : e32[si];
            d = is64 ? e32[2*di] : e32[di];
        } else {
            s = i - (NE - N_NODES); d = s;
        }
        s = min(max(s, 0), N_NODES - 1);
        d = min(max(d, 0), N_NODES - 1);
        g_src[i] = s; g_dst[i] = d;
        atomicAdd(&g_cnt[d], 1);
    }
    if (i < DIN*C1) {
        int dd = i / C1, c = i % C1;
        int h = c >> 6, f = c & 63;
        g_B1[i] = W1[(h*DIN + dd)*F1 + f];
    }
}

// ---------------- exclusive scan of in-degrees (single block) ----------------
__global__ void scan_kernel() {
    __shared__ int ssum[1024];
    const int t = threadIdx.x;
    const int per = (N_NODES + 1023) / 1024;   // 10
    int base = t * per;
    int loc[16];
    int s = 0;
#pragma unroll
    for (int i = 0; i < per; i++) {
        int idx = base + i;
        int v = (idx < N_NODES) ? g_cnt[idx] : 0;
        loc[i] = v; s += v;
    }
    ssum[t] = s;
    __syncthreads();
    for (int off = 1; off < 1024; off <<= 1) {
        int v = (t >= off) ? ssum[t - off] : 0;
        __syncthreads();
        ssum[t] += v;
        __syncthreads();
    }
    int run = (t > 0) ? ssum[t - 1] : 0;
#pragma unroll
    for (int i = 0; i < per; i++) {
        int idx = base + i;
        if (idx < N_NODES) { g_rowptr[idx] = run; run += loc[i]; }
    }
    if (t == 1023) g_rowptr[N_NODES] = NE;
}

__global__ void fill_csr() {
    int e = blockIdx.x * blockDim.x + threadIdx.x;
    if (e >= NE) return;
    int d = g_dst[e];
    int slot = atomicAdd(&g_cursor[d], 1);
    g_nbr[g_rowptr[d] + slot] = g_src[e];
}

// ---------------- GEMM1: bf16x3 tensor-core (mma.sync m16n8k16) --------------
// Block tile 128x64, 8 warps (4m x 2n), warp tile 32x32. K-chunk 16.
// v = hi_bf16 + lo_bf16; D += AH*BH + AH*BL + AL*BH  (residual ~2^-17).
// Fused alpha1 epilogue (blockIdx.x == head).
#define MMA_BF16(D, A0, A1, A2, A3, B0, B1) \
    asm("mma.sync.aligned.m16n8k16.row.col.f32.bf16.bf16.f32 " \
        "{%0,%1,%2,%3}, {%4,%5,%6,%7}, {%8,%9}, {%0,%1,%2,%3};" \
        : "+f"(D[0]), "+f"(D[1]), "+f"(D[2]), "+f"(D[3]) \
        : "r"(A0), "r"(A1), "r"(A2), "r"(A3), "r"(B0), "r"(B1))

__device__ __forceinline__ void split_pack(float v0, float v1,
                                           uint32_t& hi, uint32_t& lo) {
    __nv_bfloat162 h2 = __floats2bfloat162_rn(v0, v1);
    float r0 = v0 - __low2float(h2);
    float r1 = v1 - __high2float(h2);
    __nv_bfloat162 l2 = __floats2bfloat162_rn(r0, r1);
    hi = *(const uint32_t*)&h2;
    lo = *(const uint32_t*)&l2;
}

__global__ __launch_bounds__(256) void gemm1_kernel(const float* __restrict__ A,
                                                    const float* __restrict__ a1) {
    // stride 12 (uint32) => conflict-free fragment loads for quad pattern
    __shared__ uint32_t AsH[128][12], AsL[128][12];
    __shared__ uint32_t BsH[64][12],  BsL[64][12];
    __shared__ float sAs[64], sAn[64];
    __shared__ float salS[128][2], salN[128][2];

    const int tid = threadIdx.x;
    const int lane = tid & 31, wid = tid >> 5;
    const int wm = wid >> 1, wn = wid & 1;
    const int g = lane >> 2, tig = lane & 3;
    const int row0 = blockIdx.y * 128;
    const int h = blockIdx.x;
    const int col0 = h * 64;
    const int M = N_NODES;

    if (tid < 64) {
        sAs[tid] = __ldg(&a1[h*2*F1 + tid]);
        sAn[tid] = __ldg(&a1[h*2*F1 + F1 + tid]);
    }

    float acc[2][4][4];
#pragma unroll
    for (int mi = 0; mi < 2; mi++)
#pragma unroll
        for (int ni = 0; ni < 4; ni++)
#pragma unroll
            for (int q = 0; q < 4; q++) acc[mi][ni][q] = 0.f;

    for (int k0 = 0; k0 < DIN; k0 += 16) {
        // A tile: 128 rows x 8 k-pairs (1024 entries, 4/thread)
#pragma unroll
        for (int t = 0; t < 4; t++) {
            int idx = tid + t*256;
            int r = idx >> 3, kk = idx & 7;
            int grow = row0 + r;
            float2 v = (grow < M) ? *(const float2*)&A[(size_t)grow*DIN + k0 + 2*kk]
                                  : make_float2(0.f, 0.f);
            split_pack(v.x, v.y, AsH[r][kk], AsL[r][kk]);
        }
        // B tile: 64 cols x 8 k-pairs (512 entries, 2/thread), coalesced rows
#pragma unroll
        for (int t = 0; t < 2; t++) {
            int idx = tid + t*256;
            int kk = idx >> 6, c = idx & 63;
            float v0 = g_B1[(size_t)(k0 + 2*kk)*C1 + col0 + c];
            float v1 = g_B1[(size_t)(k0 + 2*kk + 1)*C1 + col0 + c];
            split_pack(v0, v1, BsH[c][kk], BsL[c][kk]);
        }
        __syncthreads();

        uint32_t bh[4][2], bl[4][2];
#pragma unroll
        for (int ni = 0; ni < 4; ni++) {
            int c = wn*32 + ni*8 + g;
            bh[ni][0] = BsH[c][tig];     bh[ni][1] = BsH[c][tig + 4];
            bl[ni][0] = BsL[c][tig];     bl[ni][1] = BsL[c][tig + 4];
        }
#pragma unroll
        for (int mi = 0; mi < 2; mi++) {
            int r = wm*32 + mi*16 + g;
            uint32_t ah0 = AsH[r][tig],     ah1 = AsH[r + 8][tig];
            uint32_t ah2 = AsH[r][tig + 4], ah3 = AsH[r + 8][tig + 4];
            uint32_t al0 = AsL[r][tig],     al1 = AsL[r + 8][tig];
            uint32_t al2 = AsL[r][tig + 4], al3 = AsL[r + 8][tig + 4];
#pragma unroll
            for (int ni = 0; ni < 4; ni++) {
                MMA_BF16(acc[mi][ni], ah0, ah1, ah2, ah3, bh[ni][0], bh[ni][1]);
                MMA_BF16(acc[mi][ni], ah0, ah1, ah2, ah3, bl[ni][0], bl[ni][1]);
                MMA_BF16(acc[mi][ni], al0, al1, al2, al3, bh[ni][0], bh[ni][1]);
            }
        }
        __syncthreads();
    }

    // epilogue: store proj1 + fused alpha1
#pragma unroll
    for (int mi = 0; mi < 2; mi++) {
        float s0 = 0.f, s8 = 0.f, n0 = 0.f, n8 = 0.f;
        int growA = row0 + wm*32 + mi*16 + g;
        int growB = growA + 8;
#pragma unroll
        for (int ni = 0; ni < 4; ni++) {
            float c0 = acc[mi][ni][0], c1 = acc[mi][ni][1];
            float c2 = acc[mi][ni][2], c3 = acc[mi][ni][3];
            int cl = wn*32 + ni*8 + 2*tig;
            if (growA < M)
                *(float2*)&g_proj1[(size_t)growA*C1 + col0 + cl] = make_float2(c0, c1);
            if (growB < M)
                *(float2*)&g_proj1[(size_t)growB*C1 + col0 + cl] = make_float2(c2, c3);
            float as0 = sAs[cl], as1 = sAs[cl + 1];
            float an0 = sAn[cl], an1 = sAn[cl + 1];
            s0 += c0*as0 + c1*as1;  n0 += c0*an0 + c1*an1;
            s8 += c2*as0 + c3*as1;  n8 += c2*an0 + c3*an1;
        }
#pragma unroll
        for (int o = 1; o <= 2; o <<= 1) {
            s0 += __shfl_xor_sync(FULL, s0, o);
            s8 += __shfl_xor_sync(FULL, s8, o);
            n0 += __shfl_xor_sync(FULL, n0, o);
            n8 += __shfl_xor_sync(FULL, n8, o);
        }
        if (tig == 0) {
            int rl = wm*32 + mi*16 + g;
            salS[rl][wn] = s0;  salN[rl][wn] = n0;
            salS[rl + 8][wn] = s8;  salN[rl + 8][wn] = n8;
        }
    }
    __syncthreads();
    if (tid < 128) {
        int grow = row0 + tid;
        if (grow < M) {
            g_as1[grow*H1 + h] = salS[tid][0] + salS[tid][1];
            g_an1[grow*H1 + h] = salN[tid][0] + salN[tid][1];
        }
    }
}

// ---------------- GEMM2 split-K: 64x64 tile, K-chunk 128 per z ---------------
__global__ void gemm2_kernel(const float* __restrict__ B) {
    __shared__ __align__(16) float As[16][68];
    __shared__ __align__(16) float Bs[16][64];
    const float* A = g_hbuf;
    const int M = N_NODES, N = F2, K = C1;
    const int tid = threadIdx.x;
    const int tx = tid & 15, ty = tid >> 4;
    const int row0 = blockIdx.y * 64;
    const int kz0 = blockIdx.z * (K/4);
    float* C = g_p2part + (size_t)blockIdx.z * N_NODES * F2;
    float acc[4][4];
#pragma unroll
    for (int i = 0; i < 4; i++)
#pragma unroll
        for (int j = 0; j < 4; j++) acc[i][j] = 0.f;

    for (int k0 = kz0; k0 < kz0 + K/4; k0 += 16) {
#pragma unroll
        for (int l = 0; l < 4; l++) {
            int i = tid + l*256;
            int r = i >> 4, kk = i & 15;
            int gr = row0 + r;
            As[kk][r] = (gr < M) ? A[(size_t)gr*K + k0 + kk] : 0.f;
        }
        {
            int kk = tid >> 6, c = tid & 63;
            Bs[kk][c]      = B[(size_t)(k0 + kk)*N + c];
            Bs[kk + 4][c]  = B[(size_t)(k0 + kk + 4)*N + c];
            Bs[kk + 8][c]  = B[(size_t)(k0 + kk + 8)*N + c];
            Bs[kk + 12][c] = B[(size_t)(k0 + kk + 12)*N + c];
        }
        __syncthreads();
#pragma unroll
        for (int kk = 0; kk < 16; kk++) {
            float4 av = *(const float4*)&As[kk][ty*4];
            float4 bv = *(const float4*)&Bs[kk][tx*4];
            float a[4] = {av.x, av.y, av.z, av.w};
            float b[4] = {bv.x, bv.y, bv.z, bv.w};
#pragma unroll
            for (int i = 0; i < 4; i++)
#pragma unroll
                for (int j = 0; j < 4; j++) acc[i][j] += a[i]*b[j];
        }
        __syncthreads();
    }
#pragma unroll
    for (int i = 0; i < 4; i++) {
        int gr = row0 + ty*4 + i;
        if (gr < M) {
            *(float4*)&C[(size_t)gr*N + tx*4] =
                make_float4(acc[i][0], acc[i][1], acc[i][2], acc[i][3]);
        }
    }
}

// ---------------- combine split-K partials + attention (layer 2) -------------
__global__ void alpha2_combine(const float* __restrict__ a2) {
    int t = blockIdx.x * blockDim.x + threadIdx.x;
    int w = t >> 5, lane = t & 31;
    if (w >= N_NODES) return;
    const size_t NF = (size_t)N_NODES * F2;
    size_t base = (size_t)w*F2;
    float v0 = g_p2part[base + lane]        + g_p2part[NF + base + lane]
             + g_p2part[2*NF + base + lane] + g_p2part[3*NF + base + lane];
    float v1 = g_p2part[base + lane + 32]        + g_p2part[NF + base + lane + 32]
             + g_p2part[2*NF + base + lane + 32] + g_p2part[3*NF + base + lane + 32];
    g_proj2[base + lane] = v0;
    g_proj2[base + lane + 32] = v1;
    float s  = v0*a2[lane]      + v1*a2[lane + 32];
    float tn = v0*a2[F2 + lane] + v1*a2[F2 + lane + 32];
#pragma unroll
    for (int o = 16; o; o >>= 1) {
        s  += __shfl_xor_sync(FULL, s, o);
        tn += __shfl_xor_sync(FULL, tn, o);
    }
    if (!lane) { g_as2[w] = s; g_an2[w] = tn; }
}

// ---------------- fused gather: softmax + weighted agg + ELU (layer 1) -------
__global__ void gather1() {
    int t = blockIdx.x * blockDim.x + threadIdx.x;
    int w = t >> 5, lane = t & 31;
    if (w >= N_NODES*H1) return;
    int n = w >> 3, h = w & 7;
    int beg = g_rowptr[n], end = g_rowptr[n + 1];
    float as = g_as1[n*H1 + h];

    float mx = -3.0e38f;
    for (int i = beg + lane; i < end; i += 32) {
        float v = as + g_an1[g_nbr[i]*H1 + h];
        v = (v >= 0.f) ? v : NEG_SLOPE*v;
        mx = fmaxf(mx, v);
    }
#pragma unroll
    for (int o = 16; o; o >>= 1) mx = fmaxf(mx, __shfl_xor_sync(FULL, mx, o));

    const int half = lane >> 4;
    const int fl = (lane & 15) * 4;
    const float* projh = g_proj1 + h*F1 + fl;
    float a0 = 0.f, a1v = 0.f, a2v = 0.f, a3 = 0.f, den = 0.f;
    for (int base = beg; base < end; base += 32) {
        int i = base + lane;
        int s = 0; float wgt = 0.f;
        if (i < end) {
            s = g_nbr[i];
            float v = as + g_an1[s*H1 + h];
            v = (v >= 0.f) ? v : NEG_SLOPE*v;
            wgt = __expf(v - mx);
            den += wgt;
        }
        int cnt = min(32, end - base);
        if (cnt == 32) {
#pragma unroll
            for (int j = 0; j < 16; j++) {
                int sl = 2*j + half;
                float ww = __shfl_sync(FULL, wgt, sl);
                int ss = __shfl_sync(FULL, s, sl);
                float4 p = *(const float4*)&projh[(size_t)ss*C1];
                a0 += ww*p.x; a1v += ww*p.y; a2v += ww*p.z; a3 += ww*p.w;
            }
        } else {
            int jmax = (cnt + 1) >> 1;
            for (int j = 0; j < jmax; j++) {
                int sl = 2*j + half;
                float ww = __shfl_sync(FULL, wgt, sl);
                int ss = __shfl_sync(FULL, s, sl);
                float4 p = *(const float4*)&projh[(size_t)ss*C1];
                a0 += ww*p.x; a1v += ww*p.y; a2v += ww*p.z; a3 += ww*p.w;
            }
        }
    }
    a0  += __shfl_xor_sync(FULL, a0, 16);
    a1v += __shfl_xor_sync(FULL, a1v, 16);
    a2v += __shfl_xor_sync(FULL, a2v, 16);
    a3  += __shfl_xor_sync(FULL, a3, 16);
#pragma unroll
    for (int o = 16; o; o >>= 1) den += __shfl_xor_sync(FULL, den, o);
    if (lane < 16) {
        float inv = 1.f / den;
        a0 *= inv; a1v *= inv; a2v *= inv; a3 *= inv;
        a0  = (a0  > 0.f) ? a0  : expm1f(a0);
        a1v = (a1v > 0.f) ? a1v : expm1f(a1v);
        a2v = (a2v > 0.f) ? a2v : expm1f(a2v);
        a3  = (a3  > 0.f) ? a3  : expm1f(a3);
        *(float4*)&g_hbuf[(size_t)n*C1 + h*F1 + fl] = make_float4(a0, a1v, a2v, a3);
    }
}

// ---------------- fused gather layer 2 (H2=1, mean == identity) --------------
__global__ void gather2(float* __restrict__ out) {
    int t = blockIdx.x * blockDim.x + threadIdx.x;
    int w = t >> 5, lane = t & 31;
    if (w >= N_NODES) return;
    int n = w;
    int beg = g_rowptr[n], end = g_rowptr[n + 1];
    float as = g_as2[n];

    float mx = -3.0e38f;
    for (int i = beg + lane; i < end; i += 32) {
        float v = as + g_an2[g_nbr[i]];
        v = (v >= 0.f) ? v : NEG_SLOPE*v;
        mx = fmaxf(mx, v);
    }
#pragma unroll
    for (int o = 16; o; o >>= 1) mx = fmaxf(mx, __shfl_xor_sync(FULL, mx, o));

    const int half = lane >> 4;
    const int fl = (lane & 15) * 4;
    const float* projl = g_proj2 + fl;
    float a0 = 0.f, a1v = 0.f, a2v = 0.f, a3 = 0.f, den = 0.f;
    for (int base = beg; base < end; base += 32) {
        int i = base + lane;
        int s = 0; float wgt = 0.f;
        if (i < end) {
            s = g_nbr[i];
            float v = as + g_an2[s];
            v = (v >= 0.f) ? v : NEG_SLOPE*v;
            wgt = __expf(v - mx);
            den += wgt;
        }
        int cnt = min(32, end - base);
        if (cnt == 32) {
#pragma unroll
            for (int j = 0; j < 16; j++) {
                int sl = 2*j + half;
                float ww = __shfl_sync(FULL, wgt, sl);
                int ss = __shfl_sync(FULL, s, sl);
                float4 p = *(const float4*)&projl[(size_t)ss*F2];
                a0 += ww*p.x; a1v += ww*p.y; a2v += ww*p.z; a3 += ww*p.w;
            }
        } else {
            int jmax = (cnt + 1) >> 1;
            for (int j = 0; j < jmax; j++) {
                int sl = 2*j + half;
                float ww = __shfl_sync(FULL, wgt, sl);
                int ss = __shfl_sync(FULL, s, sl);
                float4 p = *(const float4*)&projl[(size_t)ss*F2];
                a0 += ww*p.x; a1v += ww*p.y; a2v += ww*p.z; a3 += ww*p.w;
            }
        }
    }
    a0  += __shfl_xor_sync(FULL, a0, 16);
    a1v += __shfl_xor_sync(FULL, a1v, 16);
    a2v += __shfl_xor_sync(FULL, a2v, 16);
    a3  += __shfl_xor_sync(FULL, a3, 16);
#pragma unroll
    for (int o = 16; o; o >>= 1) den += __shfl_xor_sync(FULL, den, o);
    if (lane < 16) {
        float inv = 1.f / den;
        *(float4*)&out[(size_t)n*F2 + fl] =
            make_float4(a0*inv, a1v*inv, a2v*inv, a3*inv);
    }
}

// ---------------- launch -------------------------------------------------------
extern "C" void kernel_launch(void* const* d_in, const int* in_sizes, int n_in,
                              void* d_out, int out_size) {
    const float* x     = (const float*)d_in[0];
    const int*   edges = (const int*)d_in[1];
    const float* W1    = (const float*)d_in[2];
    const float* a1    = (const float*)d_in[3];
    const float* W2    = (const float*)d_in[4];
    const float* a2    = (const float*)d_in[5];
    float* out = (float*)d_out;

    void* cnt_ptr = nullptr; void* cur_ptr = nullptr;
    cudaGetSymbolAddress(&cnt_ptr, g_cnt);
    cudaGetSymbolAddress(&cur_ptr, g_cursor);
    cudaMemsetAsync(cnt_ptr, 0, N_NODES*sizeof(int));      // launch 1
    cudaMemsetAsync(cur_ptr, 0, N_NODES*sizeof(int));      // launch 2

    prep_kernel<<<(NE + 255)/256, 256>>>(edges, W1);       // launch 3
    scan_kernel<<<1, 1024>>>();                            // launch 4
    fill_csr<<<(NE + 255)/256, 256>>>();                   // launch 5

    // layer 1  (gemm1 = launch 6 -> ncu profile slot; alpha1 fused in epilogue)
    gemm1_kernel<<<dim3(C1/64, (N_NODES + 127)/128), 256>>>(x, a1);
    gather1<<<(N_NODES*H1*32 + 255)/256, 256>>>();

    // layer 2
    gemm2_kernel<<<dim3(1, (N_NODES + 63)/64, 4), 256>>>(W2);
    alpha2_combine<<<(N_NODES*32 + 255)/256, 256>>>(a2);
    gather2<<<(N_NODES*32 + 255)/256, 256>>>(out);
}